// round 7
// baseline (speedup 1.0000x reference)
#include <cuda_runtime.h>
#include <cuda_fp16.h>
#include <cstdint>
#include <math.h>

#define NN 1024
#define SS 8
#define II 128
#define FF 1024
#define MM 512

// ---------------------------------------------------------------------------
// Scratch (device globals). Pure fp16, single term.
// ---------------------------------------------------------------------------
__device__ __align__(16) __half g_xh[SS * NN * II];
__device__ __align__(16) __half g_wih[SS * FF * II];
__device__ __align__(16) __half g_wgh[SS * FF * II];
__device__ __align__(16) __half g_woh[SS * FF * II];
__device__ __align__(16) __half g_wouth[SS * MM * FF];
__device__ __align__(16) __half g_hh[SS * NN * FF];

// ---------------------------------------------------------------------------
// Helpers
// ---------------------------------------------------------------------------
__device__ __forceinline__ uint32_t smem_u32(const void* p) {
    uint32_t a;
    asm("{ .reg .u64 t; cvta.to.shared.u64 t, %1; cvt.u32.u64 %0, t; }"
        : "=r"(a) : "l"(p));
    return a;
}

__device__ __forceinline__ void ldsm4(uint32_t* r, uint32_t a) {
    asm volatile("ldmatrix.sync.aligned.m8n8.x4.shared.b16 {%0,%1,%2,%3}, [%4];"
        : "=r"(r[0]), "=r"(r[1]), "=r"(r[2]), "=r"(r[3]) : "r"(a));
}

__device__ __forceinline__ void mma_f16(float* d, const uint32_t* a,
                                        uint32_t b0, uint32_t b1) {
    asm volatile(
        "mma.sync.aligned.m16n8k16.row.col.f32.f16.f16.f32 "
        "{%0,%1,%2,%3}, {%4,%5,%6,%7}, {%8,%9}, {%0,%1,%2,%3};"
        : "+f"(d[0]), "+f"(d[1]), "+f"(d[2]), "+f"(d[3])
        : "r"(a[0]), "r"(a[1]), "r"(a[2]), "r"(a[3]), "r"(b0), "r"(b1));
}

__device__ __forceinline__ void cpasync16(uint32_t dst, const void* src) {
    asm volatile("cp.async.cg.shared.global [%0], [%1], 16;"
        :: "r"(dst), "l"(src));
}
#define CP_COMMIT() asm volatile("cp.async.commit_group;" ::: "memory")
#define CP_WAIT(n)  asm volatile("cp.async.wait_group %0;" :: "n"(n) : "memory")

__device__ __forceinline__ float sigm_fast(float x) {
    return __fdividef(1.f, 1.f + __expf(-x));
}

// ---------------------------------------------------------------------------
// Convert: fp32 -> fp16 (rn). x remapped [N][S][I] -> [S][N][I].
// 2 float4 per thread.
// ---------------------------------------------------------------------------
__global__ __launch_bounds__(256) void convert_all(
    const float* __restrict__ mod, const float* __restrict__ Wxi,
    const float* __restrict__ Wxg, const float* __restrict__ Wxo,
    const float* __restrict__ Wout)
{
    const int base = (blockIdx.x * 256 + threadIdx.x) * 2;
#pragma unroll
    for (int u = 0; u < 2; u++) {
        const int i = base + u;
        if (i < 262144) {                   // x remap
            int i4 = i & 31, n = (i >> 5) & 1023, s = i >> 15;
            float4 v = *(const float4*)(mod + (size_t)n * (SS * II) + s * II + i4 * 4);
            __half h[4] = {__float2half_rn(v.x), __float2half_rn(v.y),
                           __float2half_rn(v.z), __float2half_rn(v.w)};
            *(uint2*)(g_xh + ((size_t)s * NN + n) * II + i4 * 4) = *(uint2*)h;
            continue;
        }
        const float* src;
        __half* dh;
        size_t j;
        if (i < 524288)       { j = (size_t)(i - 262144) * 4;  src = Wxi;  dh = g_wih; }
        else if (i < 786432)  { j = (size_t)(i - 524288) * 4;  src = Wxg;  dh = g_wgh; }
        else if (i < 1048576) { j = (size_t)(i - 786432) * 4;  src = Wxo;  dh = g_woh; }
        else                  { j = (size_t)(i - 1048576) * 4; src = Wout; dh = g_wouth; }

        float4 v = *(const float4*)(src + j);
        __half h[4] = {__float2half_rn(v.x), __float2half_rn(v.y),
                       __float2half_rn(v.z), __float2half_rn(v.w)};
        *(uint2*)(dh + j) = *(uint2*)h;
    }
}

// ---------------------------------------------------------------------------
// Gates kernel: CTA tile 128(n) x 64(f), all 3 gates, K=128 resident.
// 512 threads = 16 warps (4x4), warp tile 32(n) x 16(f). Single-term fp16.
// 2 CTAs/SM. Fused LSTM epilogue -> h fp16. grid (8, 16, 8), smem 87040 B.
// ---------------------------------------------------------------------------
__global__ __launch_bounds__(512, 2) void gates_mma(
    const float* __restrict__ bi, const float* __restrict__ bg,
    const float* __restrict__ bo)
{
    extern __shared__ __half sm[];
    constexpr int PAD = 136;                 // k-stride (fp16): 272 B, ldsm-clean
    constexpr uint32_t OFF_B = 128 * PAD;    // A[128][PAD], then per-gate B[64][PAD]
    const int tid = threadIdx.x, wid = tid >> 5, lane = tid & 31;
    const int s = blockIdx.z, n0 = blockIdx.x * 128, f0 = blockIdx.y * 64;
    const uint32_t sb = smem_u32(sm);

    // ---- one-shot cp.async fill ----
    {
        const __half* sa = g_xh + ((size_t)s * NN + n0) * II;
#pragma unroll
        for (int it = 0; it < 4; it++) {
            int idx = tid + it * 512;
            int row = idx >> 4, q = idx & 15;
            cpasync16(sb + 2 * (row * PAD + q * 8), sa + (size_t)row * II + q * 8);
        }
        const __half* WH[3] = {g_wih, g_wgh, g_woh};
#pragma unroll
        for (int g = 0; g < 3; g++) {
            const __half* bh = WH[g] + ((size_t)s * FF + f0) * II;
            uint32_t dh = OFF_B + g * 64 * PAD;
#pragma unroll
            for (int it = 0; it < 2; it++) {
                int idx = tid + it * 512;
                int row = idx >> 4, q = idx & 15;
                cpasync16(sb + 2 * (dh + row * PAD + q * 8),
                          bh + (size_t)row * II + q * 8);
            }
        }
    }
    CP_COMMIT();
    CP_WAIT(0);
    __syncthreads();

    const int wm = wid & 3, wn = wid >> 2;
    const int lrA = lane & 15, lcA = (lane >> 4) << 3;
    const int lrB = ((lane >> 4) << 3) + (lane & 7), lcB = ((lane >> 3) & 1) << 3;

    float acc[3][2][2][4];
#pragma unroll
    for (int g = 0; g < 3; g++)
#pragma unroll
        for (int mb = 0; mb < 2; mb++)
#pragma unroll
            for (int nb = 0; nb < 2; nb++)
#pragma unroll
                for (int e = 0; e < 4; e++) acc[g][mb][nb][e] = 0.f;

    const uint32_t aAh = sb + 2 * ((wm * 32 + lrA) * PAD + lcA);

#pragma unroll
    for (int kk = 0; kk < 8; kk++) {
        const int k0 = kk * 16;
        uint32_t ah[2][4];
        ldsm4(ah[0], aAh + 2 * k0);
        ldsm4(ah[1], aAh + 2 * (16 * PAD + k0));
#pragma unroll
        for (int g = 0; g < 3; g++) {
            const uint32_t bgb = sb + 2 * (OFF_B + g * 64 * PAD
                                 + (wn * 16 + lrB) * PAD + k0 + lcB);
            uint32_t bh[4];
            ldsm4(bh, bgb);
#pragma unroll
            for (int mb = 0; mb < 2; mb++)
#pragma unroll
                for (int nb = 0; nb < 2; nb++)
                    mma_f16(acc[g][mb][nb], ah[mb], bh[nb * 2], bh[nb * 2 + 1]);
        }
    }

    // ---- fused LSTM epilogue: h = sigm(o) * tanh( sigm(i) * tanh(g) ) ----
#pragma unroll
    for (int nb = 0; nb < 2; nb++) {
        const int fc = f0 + wn * 16 + nb * 8 + (lane & 3) * 2;
        const float bi0 = bi[(size_t)s * FF + fc], bi1 = bi[(size_t)s * FF + fc + 1];
        const float bg0 = bg[(size_t)s * FF + fc], bg1 = bg[(size_t)s * FF + fc + 1];
        const float bo0 = bo[(size_t)s * FF + fc], bo1 = bo[(size_t)s * FF + fc + 1];
#pragma unroll
        for (int mb = 0; mb < 2; mb++)
#pragma unroll
            for (int hf = 0; hf < 2; hf++) {
                const int n = n0 + wm * 32 + mb * 16 + (lane >> 2) + hf * 8;
                const size_t off = ((size_t)s * NN + n) * FF + fc;
                float h2[2];
#pragma unroll
                for (int e = 0; e < 2; e++) {
                    float pi = acc[0][mb][nb][hf * 2 + e] + (e ? bi1 : bi0);
                    float pg = acc[1][mb][nb][hf * 2 + e] + (e ? bg1 : bg0);
                    float po = acc[2][mb][nb][hf * 2 + e] + (e ? bo1 : bo0);
                    float iv = sigm_fast(pi);
                    float gv = tanhf(pg);
                    float ov = sigm_fast(po);
                    h2[e] = ov * tanhf(iv * gv);
                }
                *(__half2*)(g_hh + off) = __floats2half2_rn(h2[0], h2[1]);
            }
    }
}

// ---------------------------------------------------------------------------
// Out kernel: CTA tile 128(n) x 128(m). 256 threads = 8 warps (2x4),
// warp tile 64(n) x 32(m). K=1024 in 32 chunks of 32, 4-stage cp.async
// pipeline with ONE sync per iteration. 2 CTAs/SM (smem 81920 B).
// grid (8, 4, 8) -> single wave at 2/SM.
// ---------------------------------------------------------------------------
__global__ __launch_bounds__(256, 2) void out_mma(
    const float* __restrict__ bout, float* __restrict__ out)
{
    extern __shared__ __half sm[];
    constexpr int PB = 40;                         // row stride (80 B, ldsm-clean)
    constexpr uint32_t TEN = 128 * PB;             // elems per tensor per stage
    constexpr uint32_t STG_B = 2u * TEN * 2;       // 20480 B per stage, 4 stages

    const int tid = threadIdx.x, wid = tid >> 5, lane = tid & 31;
    const int s = blockIdx.z, n0 = blockIdx.x * 128, m0 = blockIdx.y * 128;
    const uint32_t sb = smem_u32(sm);

    const __half* gA = g_hh    + ((size_t)s * NN + n0) * FF;
    const __half* gB = g_wouth + ((size_t)s * MM + m0) * FF;

    auto load = [&](int ch, int stg) {
        const int kc = ch * 32;
        const uint32_t base = sb + (uint32_t)stg * STG_B;
#pragma unroll
        for (int it = 0; it < 2; it++) {
            int idx = tid + it * 256;
            int row = idx >> 2, q = idx & 3;
            const uint32_t d = 2 * (row * PB + q * 8);
            const size_t so = (size_t)row * FF + kc + q * 8;
            cpasync16(base + d,           gA + so);
            cpasync16(base + 2 * TEN + d, gB + so);
        }
    };

    const int wm = wid & 1, wn = wid >> 1;
    const int lrA = lane & 15, lcA = (lane >> 4) << 3;
    const int lrB = ((lane >> 4) << 3) + (lane & 7), lcB = ((lane >> 3) & 1) << 3;

    float acc[4][4][4];
#pragma unroll
    for (int mb = 0; mb < 4; mb++)
#pragma unroll
        for (int nb = 0; nb < 4; nb++)
#pragma unroll
            for (int e = 0; e < 4; e++) acc[mb][nb][e] = 0.f;

    load(0, 0); CP_COMMIT();
    load(1, 1); CP_COMMIT();
    load(2, 2); CP_COMMIT();

#pragma unroll 1
    for (int ch = 0; ch < 32; ch++) {
        CP_WAIT(2);
        __syncthreads();
        // stage (ch+3)%4 was consumed at iteration ch-1 (sync above protects it)
        if (ch + 3 < 32) load(ch + 3, (ch + 3) & 3);
        CP_COMMIT();

        const int stg = ch & 3;
        const uint32_t base = sb + (uint32_t)stg * STG_B;
        const uint32_t aA = base + 2 * ((wm * 64 + lrA) * PB + lcA);
        const uint32_t aB = base + 2 * (TEN + (wn * 32 + lrB) * PB + lcB);

#pragma unroll
        for (int kk = 0; kk < 2; kk++) {
            const int k0 = kk * 16;
            uint32_t ah[4][4], bh[2][4];
#pragma unroll
            for (int mb = 0; mb < 4; mb++)
                ldsm4(ah[mb], aA + 2 * (mb * 16 * PB + k0));
#pragma unroll
            for (int p = 0; p < 2; p++)
                ldsm4(bh[p], aB + 2 * (p * 16 * PB + k0));
#pragma unroll
            for (int mb = 0; mb < 4; mb++)
#pragma unroll
                for (int nb = 0; nb < 4; nb++)
                    mma_f16(acc[mb][nb], ah[mb],
                            bh[nb >> 1][(nb & 1) * 2], bh[nb >> 1][(nb & 1) * 2 + 1]);
        }
    }

    // ---- epilogue: bias + fp32 store ----
#pragma unroll
    for (int nb = 0; nb < 4; nb++) {
        const int mc = m0 + wn * 32 + nb * 8 + (lane & 3) * 2;
        const float b0 = bout[(size_t)s * MM + mc];
        const float b1 = bout[(size_t)s * MM + mc + 1];
#pragma unroll
        for (int mb = 0; mb < 4; mb++)
#pragma unroll
            for (int hf = 0; hf < 2; hf++) {
                const int n = n0 + wm * 64 + mb * 16 + (lane >> 2) + hf * 8;
                float2 v = make_float2(acc[mb][nb][hf * 2] + b0,
                                       acc[mb][nb][hf * 2 + 1] + b1);
                *(float2*)(out + (size_t)n * (SS * MM) + s * MM + mc) = v;
            }
    }
}

// ---------------------------------------------------------------------------
// Launch. Inputs: modulation, Wxi, Whi, bi, Wxf, Whf, bf, Wxg, Whg, bg,
// Wxo, Who, bo, Wout, bout. h0 = c0 = 0 kills Whi/Wxf/Whf/bf/Whg/Who.
// ---------------------------------------------------------------------------
extern "C" void kernel_launch(void* const* d_in, const int* in_sizes, int n_in,
                              void* d_out, int out_size) {
    const float* mod  = (const float*)d_in[0];
    const float* Wxi  = (const float*)d_in[1];
    const float* bi   = (const float*)d_in[3];
    const float* Wxg  = (const float*)d_in[7];
    const float* bg   = (const float*)d_in[9];
    const float* Wxo  = (const float*)d_in[10];
    const float* bo   = (const float*)d_in[12];
    const float* Wout = (const float*)d_in[13];
    const float* bout = (const float*)d_in[14];
    float* out = (float*)d_out;

    cudaFuncSetAttribute(gates_mma, cudaFuncAttributeMaxDynamicSharedMemorySize, 87040);
    cudaFuncSetAttribute(out_mma,   cudaFuncAttributeMaxDynamicSharedMemorySize, 81920);

    convert_all<<<4096, 256>>>(mod, Wxi, Wxg, Wxo, Wout);

    dim3 gGates(NN / 128, FF / 64, SS);   // (8, 16, 8)
    gates_mma<<<gGates, 512, 87040>>>(bi, bg, bo);

    dim3 gOut(NN / 128, MM / 128, SS);    // (8, 4, 8)
    out_mma<<<gOut, 256, 81920>>>(bout, out);
}

// round 8
// speedup vs baseline: 1.4855x; 1.4855x over previous
#include <cuda_runtime.h>
#include <cuda_fp16.h>
#include <cstdint>
#include <math.h>

#define NN 1024
#define SS 8
#define II 128
#define FF 1024
#define MM 512

// ---------------------------------------------------------------------------
// Scratch (device globals). Pure fp16, single term.
// ---------------------------------------------------------------------------
__device__ __align__(16) __half g_xh[SS * NN * II];
__device__ __align__(16) __half g_wih[SS * FF * II];
__device__ __align__(16) __half g_wgh[SS * FF * II];
__device__ __align__(16) __half g_woh[SS * FF * II];
__device__ __align__(16) __half g_wouth[SS * MM * FF];
__device__ __align__(16) __half g_hh[SS * NN * FF];

// ---------------------------------------------------------------------------
// Helpers
// ---------------------------------------------------------------------------
__device__ __forceinline__ uint32_t smem_u32(const void* p) {
    uint32_t a;
    asm("{ .reg .u64 t; cvta.to.shared.u64 t, %1; cvt.u32.u64 %0, t; }"
        : "=r"(a) : "l"(p));
    return a;
}

__device__ __forceinline__ void ldsm4(uint32_t* r, uint32_t a) {
    asm volatile("ldmatrix.sync.aligned.m8n8.x4.shared.b16 {%0,%1,%2,%3}, [%4];"
        : "=r"(r[0]), "=r"(r[1]), "=r"(r[2]), "=r"(r[3]) : "r"(a));
}

__device__ __forceinline__ void mma_f16(float* d, const uint32_t* a,
                                        uint32_t b0, uint32_t b1) {
    asm volatile(
        "mma.sync.aligned.m16n8k16.row.col.f32.f16.f16.f32 "
        "{%0,%1,%2,%3}, {%4,%5,%6,%7}, {%8,%9}, {%0,%1,%2,%3};"
        : "+f"(d[0]), "+f"(d[1]), "+f"(d[2]), "+f"(d[3])
        : "r"(a[0]), "r"(a[1]), "r"(a[2]), "r"(a[3]), "r"(b0), "r"(b1));
}

__device__ __forceinline__ void cpasync16(uint32_t dst, const void* src) {
    asm volatile("cp.async.cg.shared.global [%0], [%1], 16;"
        :: "r"(dst), "l"(src));
}
#define CP_COMMIT() asm volatile("cp.async.commit_group;" ::: "memory")
#define CP_WAIT(n)  asm volatile("cp.async.wait_group %0;" :: "n"(n) : "memory")

__device__ __forceinline__ float sigm_fast(float x) {
    return __fdividef(1.f, 1.f + __expf(-x));
}

// ---------------------------------------------------------------------------
// Convert: fp32 -> fp16 (round-to-nearest). x remapped [N][S][I] -> [S][N][I].
// ---------------------------------------------------------------------------
__global__ __launch_bounds__(256) void convert_all(
    const float* __restrict__ mod, const float* __restrict__ Wxi,
    const float* __restrict__ Wxg, const float* __restrict__ Wxo,
    const float* __restrict__ Wout)
{
    const int i = blockIdx.x * 256 + threadIdx.x;
    if (i < 262144) {                       // x remap
        int i4 = i & 31, n = (i >> 5) & 1023, s = i >> 15;
        float4 v = *(const float4*)(mod + (size_t)n * (SS * II) + s * II + i4 * 4);
        __half h[4] = {__float2half_rn(v.x), __float2half_rn(v.y),
                       __float2half_rn(v.z), __float2half_rn(v.w)};
        *(uint2*)(g_xh + ((size_t)s * NN + n) * II + i4 * 4) = *(uint2*)h;
        return;
    }
    const float* src;
    __half* dh;
    size_t j;
    if (i < 524288)       { j = (size_t)(i - 262144) * 4;  src = Wxi;  dh = g_wih; }
    else if (i < 786432)  { j = (size_t)(i - 524288) * 4;  src = Wxg;  dh = g_wgh; }
    else if (i < 1048576) { j = (size_t)(i - 786432) * 4;  src = Wxo;  dh = g_woh; }
    else                  { j = (size_t)(i - 1048576) * 4; src = Wout; dh = g_wouth; }

    float4 v = *(const float4*)(src + j);
    __half h[4] = {__float2half_rn(v.x), __float2half_rn(v.y),
                   __float2half_rn(v.z), __float2half_rn(v.w)};
    *(uint2*)(dh + j) = *(uint2*)h;
}

// ---------------------------------------------------------------------------
// Gates kernel: CTA tile 128(n) x 64(f), all 3 gates, K=128 resident.
// 512 threads = 16 warps (4x4), warp tile 32(n) x 16(f). Single-term fp16.
// Fused LSTM epilogue -> h fp16. grid (8, 16, 8), smem 87040 B.
// ---------------------------------------------------------------------------
__global__ __launch_bounds__(512, 1) void gates_mma(
    const float* __restrict__ bi, const float* __restrict__ bg,
    const float* __restrict__ bo)
{
    extern __shared__ __half sm[];
    constexpr int PAD = 136;                 // k-stride (fp16): 272 B, ldsm-clean
    constexpr uint32_t OFF_B = 128 * PAD;    // A[128][PAD], then per-gate B[64][PAD]
    const int tid = threadIdx.x, wid = tid >> 5, lane = tid & 31;
    const int s = blockIdx.z, n0 = blockIdx.x * 128, f0 = blockIdx.y * 64;
    const uint32_t sb = smem_u32(sm);

    // ---- one-shot cp.async fill ----
    {
        const __half* sa = g_xh + ((size_t)s * NN + n0) * II;
#pragma unroll
        for (int it = 0; it < 4; it++) {
            int idx = tid + it * 512;
            int row = idx >> 4, q = idx & 15;
            cpasync16(sb + 2 * (row * PAD + q * 8), sa + (size_t)row * II + q * 8);
        }
        const __half* WH[3] = {g_wih, g_wgh, g_woh};
#pragma unroll
        for (int g = 0; g < 3; g++) {
            const __half* bh = WH[g] + ((size_t)s * FF + f0) * II;
            uint32_t dh = OFF_B + g * 64 * PAD;
#pragma unroll
            for (int it = 0; it < 2; it++) {
                int idx = tid + it * 512;
                int row = idx >> 4, q = idx & 15;
                cpasync16(sb + 2 * (dh + row * PAD + q * 8),
                          bh + (size_t)row * II + q * 8);
            }
        }
    }
    CP_COMMIT();
    CP_WAIT(0);
    __syncthreads();

    const int wm = wid & 3, wn = wid >> 2;
    const int lrA = lane & 15, lcA = (lane >> 4) << 3;
    const int lrB = ((lane >> 4) << 3) + (lane & 7), lcB = ((lane >> 3) & 1) << 3;

    float acc[3][2][2][4];
#pragma unroll
    for (int g = 0; g < 3; g++)
#pragma unroll
        for (int mb = 0; mb < 2; mb++)
#pragma unroll
            for (int nb = 0; nb < 2; nb++)
#pragma unroll
                for (int e = 0; e < 4; e++) acc[g][mb][nb][e] = 0.f;

    const uint32_t aAh = sb + 2 * ((wm * 32 + lrA) * PAD + lcA);

#pragma unroll
    for (int kk = 0; kk < 8; kk++) {
        const int k0 = kk * 16;
        uint32_t ah[2][4];
        ldsm4(ah[0], aAh + 2 * k0);
        ldsm4(ah[1], aAh + 2 * (16 * PAD + k0));
#pragma unroll
        for (int g = 0; g < 3; g++) {
            const uint32_t bgb = sb + 2 * (OFF_B + g * 64 * PAD
                                 + (wn * 16 + lrB) * PAD + k0 + lcB);
            uint32_t bh[4];
            ldsm4(bh, bgb);
#pragma unroll
            for (int mb = 0; mb < 2; mb++)
#pragma unroll
                for (int nb = 0; nb < 2; nb++)
                    mma_f16(acc[g][mb][nb], ah[mb], bh[nb * 2], bh[nb * 2 + 1]);
        }
    }

    // ---- fused LSTM epilogue: h = sigm(o) * tanh( sigm(i) * tanh(g) ) ----
#pragma unroll
    for (int nb = 0; nb < 2; nb++) {
        const int fc = f0 + wn * 16 + nb * 8 + (lane & 3) * 2;
        const float bi0 = bi[(size_t)s * FF + fc], bi1 = bi[(size_t)s * FF + fc + 1];
        const float bg0 = bg[(size_t)s * FF + fc], bg1 = bg[(size_t)s * FF + fc + 1];
        const float bo0 = bo[(size_t)s * FF + fc], bo1 = bo[(size_t)s * FF + fc + 1];
#pragma unroll
        for (int mb = 0; mb < 2; mb++)
#pragma unroll
            for (int hf = 0; hf < 2; hf++) {
                const int n = n0 + wm * 32 + mb * 16 + (lane >> 2) + hf * 8;
                const size_t off = ((size_t)s * NN + n) * FF + fc;
                float h2[2];
#pragma unroll
                for (int e = 0; e < 2; e++) {
                    float pi = acc[0][mb][nb][hf * 2 + e] + (e ? bi1 : bi0);
                    float pg = acc[1][mb][nb][hf * 2 + e] + (e ? bg1 : bg0);
                    float po = acc[2][mb][nb][hf * 2 + e] + (e ? bo1 : bo0);
                    float iv = sigm_fast(pi);
                    float gv = tanhf(pg);
                    float ov = sigm_fast(po);
                    h2[e] = ov * tanhf(iv * gv);
                }
                *(__half2*)(g_hh + off) = __floats2half2_rn(h2[0], h2[1]);
            }
    }
}

// ---------------------------------------------------------------------------
// Out kernel: CTA tile 128(n) x 128(m). 256 threads = 8 warps (2x4),
// warp tile 64(n) x 32(m). K=1024 in 32 chunks of 32, 3-stage cp.async.
// Single-term fp16. 2 CTAs/SM (smem 61440 B). grid (8, 4, 8).
// ---------------------------------------------------------------------------
__global__ __launch_bounds__(256, 2) void out_mma(
    const float* __restrict__ bout, float* __restrict__ out)
{
    extern __shared__ __half sm[];
    constexpr int PB = 40;                         // row stride (80 B, ldsm-clean)
    constexpr uint32_t TEN = 128 * PB;             // elems per tensor per stage
    constexpr uint32_t STG_B = 2u * TEN * 2;       // 20480 B per stage

    const int tid = threadIdx.x, wid = tid >> 5, lane = tid & 31;
    const int s = blockIdx.z, n0 = blockIdx.x * 128, m0 = blockIdx.y * 128;
    const uint32_t sb = smem_u32(sm);

    const __half* gA = g_hh    + ((size_t)s * NN + n0) * FF;
    const __half* gB = g_wouth + ((size_t)s * MM + m0) * FF;

    auto load = [&](int ch, int stg) {
        const int kc = ch * 32;
        const uint32_t base = sb + (uint32_t)stg * STG_B;
#pragma unroll
        for (int it = 0; it < 2; it++) {
            int idx = tid + it * 256;
            int row = idx >> 2, q = idx & 3;
            const uint32_t d = 2 * (row * PB + q * 8);
            const size_t so = (size_t)row * FF + kc + q * 8;
            cpasync16(base + d,           gA + so);
            cpasync16(base + 2 * TEN + d, gB + so);
        }
    };

    const int wm = wid & 1, wn = wid >> 1;
    const int lrA = lane & 15, lcA = (lane >> 4) << 3;
    const int lrB = ((lane >> 4) << 3) + (lane & 7), lcB = ((lane >> 3) & 1) << 3;

    float acc[4][4][4];
#pragma unroll
    for (int mb = 0; mb < 4; mb++)
#pragma unroll
        for (int nb = 0; nb < 4; nb++)
#pragma unroll
            for (int e = 0; e < 4; e++) acc[mb][nb][e] = 0.f;

    load(0, 0); CP_COMMIT();
    load(1, 1); CP_COMMIT();
    load(2, 2); CP_COMMIT();

#pragma unroll 1
    for (int ch = 0; ch < 32; ch++) {
        CP_WAIT(2);
        __syncthreads();

        const int stg = ch % 3;
        const uint32_t base = sb + (uint32_t)stg * STG_B;
        const uint32_t aA = base + 2 * ((wm * 64 + lrA) * PB + lcA);
        const uint32_t aB = base + 2 * (TEN + (wn * 32 + lrB) * PB + lcB);

#pragma unroll
        for (int kk = 0; kk < 2; kk++) {
            const int k0 = kk * 16;
            uint32_t ah[4][4], bh[2][4];
#pragma unroll
            for (int mb = 0; mb < 4; mb++)
                ldsm4(ah[mb], aA + 2 * (mb * 16 * PB + k0));
#pragma unroll
            for (int p = 0; p < 2; p++)
                ldsm4(bh[p], aB + 2 * (p * 16 * PB + k0));
#pragma unroll
            for (int mb = 0; mb < 4; mb++)
#pragma unroll
                for (int nb = 0; nb < 4; nb++)
                    mma_f16(acc[mb][nb], ah[mb],
                            bh[nb >> 1][(nb & 1) * 2], bh[nb >> 1][(nb & 1) * 2 + 1]);
        }
        __syncthreads();
        if (ch + 3 < 32) load(ch + 3, stg);
        CP_COMMIT();
    }

    // ---- epilogue: bias + fp32 store ----
#pragma unroll
    for (int nb = 0; nb < 4; nb++) {
        const int mc = m0 + wn * 32 + nb * 8 + (lane & 3) * 2;
        const float b0 = bout[(size_t)s * MM + mc];
        const float b1 = bout[(size_t)s * MM + mc + 1];
#pragma unroll
        for (int mb = 0; mb < 4; mb++)
#pragma unroll
            for (int hf = 0; hf < 2; hf++) {
                const int n = n0 + wm * 64 + mb * 16 + (lane >> 2) + hf * 8;
                float2 v = make_float2(acc[mb][nb][hf * 2] + b0,
                                       acc[mb][nb][hf * 2 + 1] + b1);
                *(float2*)(out + (size_t)n * (SS * MM) + s * MM + mc) = v;
            }
    }
}

// ---------------------------------------------------------------------------
// Launch. Inputs: modulation, Wxi, Whi, bi, Wxf, Whf, bf, Wxg, Whg, bg,
// Wxo, Who, bo, Wout, bout. h0 = c0 = 0 kills Whi/Wxf/Whf/bf/Whg/Who.
// ---------------------------------------------------------------------------
extern "C" void kernel_launch(void* const* d_in, const int* in_sizes, int n_in,
                              void* d_out, int out_size) {
    const float* mod  = (const float*)d_in[0];
    const float* Wxi  = (const float*)d_in[1];
    const float* bi   = (const float*)d_in[3];
    const float* Wxg  = (const float*)d_in[7];
    const float* bg   = (const float*)d_in[9];
    const float* Wxo  = (const float*)d_in[10];
    const float* bo   = (const float*)d_in[12];
    const float* Wout = (const float*)d_in[13];
    const float* bout = (const float*)d_in[14];
    float* out = (float*)d_out;

    cudaFuncSetAttribute(gates_mma, cudaFuncAttributeMaxDynamicSharedMemorySize, 87040);
    cudaFuncSetAttribute(out_mma,   cudaFuncAttributeMaxDynamicSharedMemorySize, 61440);

    convert_all<<<8192, 256>>>(mod, Wxi, Wxg, Wxo, Wout);

    dim3 gGates(NN / 128, FF / 64, SS);   // (8, 16, 8)
    gates_mma<<<gGates, 512, 87040>>>(bi, bg, bo);

    dim3 gOut(NN / 128, MM / 128, SS);    // (8, 4, 8)
    out_mma<<<gOut, 256, 61440>>>(bout, out);
}

// round 9
// speedup vs baseline: 1.5207x; 1.0237x over previous
#include <cuda_runtime.h>
#include <cuda_fp16.h>
#include <cstdint>
#include <math.h>

#define NN 1024
#define SS 8
#define II 128
#define FF 1024
#define MM 512

// ---------------------------------------------------------------------------
// Scratch (device globals). Pure fp16, single term.
// ---------------------------------------------------------------------------
__device__ __align__(16) __half g_xh[SS * NN * II];
__device__ __align__(16) __half g_wih[SS * FF * II];
__device__ __align__(16) __half g_wgh[SS * FF * II];
__device__ __align__(16) __half g_woh[SS * FF * II];
__device__ __align__(16) __half g_wouth[SS * MM * FF];
__device__ __align__(16) __half g_hh[SS * NN * FF];

// ---------------------------------------------------------------------------
// Helpers
// ---------------------------------------------------------------------------
__device__ __forceinline__ uint32_t smem_u32(const void* p) {
    uint32_t a;
    asm("{ .reg .u64 t; cvta.to.shared.u64 t, %1; cvt.u32.u64 %0, t; }"
        : "=r"(a) : "l"(p));
    return a;
}

__device__ __forceinline__ void ldsm4(uint32_t* r, uint32_t a) {
    asm volatile("ldmatrix.sync.aligned.m8n8.x4.shared.b16 {%0,%1,%2,%3}, [%4];"
        : "=r"(r[0]), "=r"(r[1]), "=r"(r[2]), "=r"(r[3]) : "r"(a));
}

__device__ __forceinline__ void mma_f16(float* d, const uint32_t* a,
                                        uint32_t b0, uint32_t b1) {
    asm volatile(
        "mma.sync.aligned.m16n8k16.row.col.f32.f16.f16.f32 "
        "{%0,%1,%2,%3}, {%4,%5,%6,%7}, {%8,%9}, {%0,%1,%2,%3};"
        : "+f"(d[0]), "+f"(d[1]), "+f"(d[2]), "+f"(d[3])
        : "r"(a[0]), "r"(a[1]), "r"(a[2]), "r"(a[3]), "r"(b0), "r"(b1));
}

__device__ __forceinline__ void cpasync16(uint32_t dst, const void* src) {
    asm volatile("cp.async.cg.shared.global [%0], [%1], 16;"
        :: "r"(dst), "l"(src));
}
#define CP_COMMIT() asm volatile("cp.async.commit_group;" ::: "memory")
#define CP_WAIT(n)  asm volatile("cp.async.wait_group %0;" :: "n"(n) : "memory")

__device__ __forceinline__ float sigm_fast(float x) {
    return __fdividef(1.f, 1.f + __expf(-x));
}

// ---------------------------------------------------------------------------
// convert_xw: fp32 -> fp16 for x (remapped [N][S][I] -> [S][N][I]) and the
// three gate weights. 1,048,576 float4 items, grid 4096 x 256.
// ---------------------------------------------------------------------------
__global__ __launch_bounds__(256) void convert_xw(
    const float* __restrict__ mod, const float* __restrict__ Wxi,
    const float* __restrict__ Wxg, const float* __restrict__ Wxo)
{
    const int i = blockIdx.x * 256 + threadIdx.x;
    if (i < 262144) {                       // x remap
        int i4 = i & 31, n = (i >> 5) & 1023, s = i >> 15;
        float4 v = *(const float4*)(mod + (size_t)n * (SS * II) + s * II + i4 * 4);
        __half h[4] = {__float2half_rn(v.x), __float2half_rn(v.y),
                       __float2half_rn(v.z), __float2half_rn(v.w)};
        *(uint2*)(g_xh + ((size_t)s * NN + n) * II + i4 * 4) = *(uint2*)h;
        return;
    }
    const float* src;
    __half* dh;
    size_t j;
    if (i < 524288)      { j = (size_t)(i - 262144) * 4; src = Wxi; dh = g_wih; }
    else if (i < 786432) { j = (size_t)(i - 524288) * 4; src = Wxg; dh = g_wgh; }
    else                 { j = (size_t)(i - 786432) * 4; src = Wxo; dh = g_woh; }

    float4 v = *(const float4*)(src + j);
    __half h[4] = {__float2half_rn(v.x), __float2half_rn(v.y),
                   __float2half_rn(v.z), __float2half_rn(v.w)};
    *(uint2*)(dh + j) = *(uint2*)h;
}

// ---------------------------------------------------------------------------
// Gates kernel + Wout conversion piggyback.
// Blocks [0,1024): CTA tile 128(n) x 64(f), all 3 gates, K=128 resident.
//   512 threads = 16 warps (4x4), warp tile 32(n) x 16(f). Single-term fp16.
//   Fused LSTM epilogue -> h fp16. smem 87040 B.
// Blocks [1024,1536): convert Wout fp32 -> g_wouth fp16 (overlaps with the
//   HMMA-bound gates blocks; memory pipe is otherwise idle).
// grid 1536 x 512.
// ---------------------------------------------------------------------------
__global__ __launch_bounds__(512, 1) void gates_mma(
    const float* __restrict__ bi, const float* __restrict__ bg,
    const float* __restrict__ bo, const float* __restrict__ Wout)
{
    const int bx = blockIdx.x;
    const int tid = threadIdx.x;

    if (bx >= 1024) {                       // ---- Wout conversion blocks ----
        const int cb = bx - 1024;           // 0..511, 2048 float4 each
        const float4* src = (const float4*)Wout;
#pragma unroll
        for (int it = 0; it < 4; it++) {
            size_t j = (size_t)cb * 2048 + it * 512 + tid;
            float4 v = src[j];
            __half h[4] = {__float2half_rn(v.x), __float2half_rn(v.y),
                           __float2half_rn(v.z), __float2half_rn(v.w)};
            *(uint2*)(g_wouth + j * 4) = *(uint2*)h;
        }
        return;
    }

    extern __shared__ __half sm[];
    constexpr int PAD = 136;                 // k-stride (fp16): 272 B, ldsm-clean
    constexpr uint32_t OFF_B = 128 * PAD;    // A[128][PAD], then per-gate B[64][PAD]
    const int wid = tid >> 5, lane = tid & 31;
    const int s = bx >> 7, f0 = ((bx >> 3) & 15) * 64, n0 = (bx & 7) * 128;
    const uint32_t sb = smem_u32(sm);

    // ---- one-shot cp.async fill ----
    {
        const __half* sa = g_xh + ((size_t)s * NN + n0) * II;
#pragma unroll
        for (int it = 0; it < 4; it++) {
            int idx = tid + it * 512;
            int row = idx >> 4, q = idx & 15;
            cpasync16(sb + 2 * (row * PAD + q * 8), sa + (size_t)row * II + q * 8);
        }
        const __half* WH[3] = {g_wih, g_wgh, g_woh};
#pragma unroll
        for (int g = 0; g < 3; g++) {
            const __half* bh = WH[g] + ((size_t)s * FF + f0) * II;
            uint32_t dh = OFF_B + g * 64 * PAD;
#pragma unroll
            for (int it = 0; it < 2; it++) {
                int idx = tid + it * 512;
                int row = idx >> 4, q = idx & 15;
                cpasync16(sb + 2 * (dh + row * PAD + q * 8),
                          bh + (size_t)row * II + q * 8);
            }
        }
    }
    CP_COMMIT();
    CP_WAIT(0);
    __syncthreads();

    const int wm = wid & 3, wn = wid >> 2;
    const int lrA = lane & 15, lcA = (lane >> 4) << 3;
    const int lrB = ((lane >> 4) << 3) + (lane & 7), lcB = ((lane >> 3) & 1) << 3;

    float acc[3][2][2][4];
#pragma unroll
    for (int g = 0; g < 3; g++)
#pragma unroll
        for (int mb = 0; mb < 2; mb++)
#pragma unroll
            for (int nb = 0; nb < 2; nb++)
#pragma unroll
                for (int e = 0; e < 4; e++) acc[g][mb][nb][e] = 0.f;

    const uint32_t aAh = sb + 2 * ((wm * 32 + lrA) * PAD + lcA);

#pragma unroll
    for (int kk = 0; kk < 8; kk++) {
        const int k0 = kk * 16;
        uint32_t ah[2][4];
        ldsm4(ah[0], aAh + 2 * k0);
        ldsm4(ah[1], aAh + 2 * (16 * PAD + k0));
#pragma unroll
        for (int g = 0; g < 3; g++) {
            const uint32_t bgb = sb + 2 * (OFF_B + g * 64 * PAD
                                 + (wn * 16 + lrB) * PAD + k0 + lcB);
            uint32_t bh[4];
            ldsm4(bh, bgb);
#pragma unroll
            for (int mb = 0; mb < 2; mb++)
#pragma unroll
                for (int nb = 0; nb < 2; nb++)
                    mma_f16(acc[g][mb][nb], ah[mb], bh[nb * 2], bh[nb * 2 + 1]);
        }
    }

    // ---- fused LSTM epilogue: h = sigm(o) * tanh( sigm(i) * tanh(g) ) ----
#pragma unroll
    for (int nb = 0; nb < 2; nb++) {
        const int fc = f0 + wn * 16 + nb * 8 + (lane & 3) * 2;
        const float bi0 = bi[(size_t)s * FF + fc], bi1 = bi[(size_t)s * FF + fc + 1];
        const float bg0 = bg[(size_t)s * FF + fc], bg1 = bg[(size_t)s * FF + fc + 1];
        const float bo0 = bo[(size_t)s * FF + fc], bo1 = bo[(size_t)s * FF + fc + 1];
#pragma unroll
        for (int mb = 0; mb < 2; mb++)
#pragma unroll
            for (int hf = 0; hf < 2; hf++) {
                const int n = n0 + wm * 32 + mb * 16 + (lane >> 2) + hf * 8;
                const size_t off = ((size_t)s * NN + n) * FF + fc;
                float h2[2];
#pragma unroll
                for (int e = 0; e < 2; e++) {
                    float pi = acc[0][mb][nb][hf * 2 + e] + (e ? bi1 : bi0);
                    float pg = acc[1][mb][nb][hf * 2 + e] + (e ? bg1 : bg0);
                    float po = acc[2][mb][nb][hf * 2 + e] + (e ? bo1 : bo0);
                    float iv = sigm_fast(pi);
                    float gv = tanhf(pg);
                    float ov = sigm_fast(po);
                    h2[e] = ov * tanhf(iv * gv);
                }
                *(__half2*)(g_hh + off) = __floats2half2_rn(h2[0], h2[1]);
            }
    }
}

// ---------------------------------------------------------------------------
// Out kernel: CTA tile 128(n) x 128(m). 256 threads = 8 warps (2x4),
// warp tile 64(n) x 32(m). K=1024 in 32 chunks of 32, 4-stage cp.async
// pipeline with ONE sync per iteration. 2 CTAs/SM (smem 81920 B).
// grid (8, 4, 8) -> single wave at 2/SM.
// ---------------------------------------------------------------------------
__global__ __launch_bounds__(256, 2) void out_mma(
    const float* __restrict__ bout, float* __restrict__ out)
{
    extern __shared__ __half sm[];
    constexpr int PB = 40;                         // row stride (80 B, ldsm-clean)
    constexpr uint32_t TEN = 128 * PB;             // elems per tensor per stage
    constexpr uint32_t STG_B = 2u * TEN * 2;       // 20480 B per stage, 4 stages

    const int tid = threadIdx.x, wid = tid >> 5, lane = tid & 31;
    const int s = blockIdx.z, n0 = blockIdx.x * 128, m0 = blockIdx.y * 128;
    const uint32_t sb = smem_u32(sm);

    const __half* gA = g_hh    + ((size_t)s * NN + n0) * FF;
    const __half* gB = g_wouth + ((size_t)s * MM + m0) * FF;

    auto load = [&](int ch, int stg) {
        const int kc = ch * 32;
        const uint32_t base = sb + (uint32_t)stg * STG_B;
#pragma unroll
        for (int it = 0; it < 2; it++) {
            int idx = tid + it * 256;
            int row = idx >> 2, q = idx & 3;
            const uint32_t d = 2 * (row * PB + q * 8);
            const size_t so = (size_t)row * FF + kc + q * 8;
            cpasync16(base + d,           gA + so);
            cpasync16(base + 2 * TEN + d, gB + so);
        }
    };

    const int wm = wid & 1, wn = wid >> 1;
    const int lrA = lane & 15, lcA = (lane >> 4) << 3;
    const int lrB = ((lane >> 4) << 3) + (lane & 7), lcB = ((lane >> 3) & 1) << 3;

    float acc[4][4][4];
#pragma unroll
    for (int mb = 0; mb < 4; mb++)
#pragma unroll
        for (int nb = 0; nb < 4; nb++)
#pragma unroll
            for (int e = 0; e < 4; e++) acc[mb][nb][e] = 0.f;

    load(0, 0); CP_COMMIT();
    load(1, 1); CP_COMMIT();
    load(2, 2); CP_COMMIT();

#pragma unroll 1
    for (int ch = 0; ch < 32; ch++) {
        CP_WAIT(2);
        __syncthreads();
        // sync above also guarantees stage (ch+3)&3 (consumed at ch-1) is free
        if (ch + 3 < 32) load(ch + 3, (ch + 3) & 3);
        CP_COMMIT();

        const int stg = ch & 3;
        const uint32_t base = sb + (uint32_t)stg * STG_B;
        const uint32_t aA = base + 2 * ((wm * 64 + lrA) * PB + lcA);
        const uint32_t aB = base + 2 * (TEN + (wn * 32 + lrB) * PB + lcB);

#pragma unroll
        for (int kk = 0; kk < 2; kk++) {
            const int k0 = kk * 16;
            uint32_t ah[4][4], bh[2][4];
#pragma unroll
            for (int mb = 0; mb < 4; mb++)
                ldsm4(ah[mb], aA + 2 * (mb * 16 * PB + k0));
#pragma unroll
            for (int p = 0; p < 2; p++)
                ldsm4(bh[p], aB + 2 * (p * 16 * PB + k0));
#pragma unroll
            for (int mb = 0; mb < 4; mb++)
#pragma unroll
                for (int nb = 0; nb < 4; nb++)
                    mma_f16(acc[mb][nb], ah[mb],
                            bh[nb >> 1][(nb & 1) * 2], bh[nb >> 1][(nb & 1) * 2 + 1]);
        }
    }

    // ---- epilogue: bias + fp32 store ----
#pragma unroll
    for (int nb = 0; nb < 4; nb++) {
        const int mc = m0 + wn * 32 + nb * 8 + (lane & 3) * 2;
        const float b0 = bout[(size_t)s * MM + mc];
        const float b1 = bout[(size_t)s * MM + mc + 1];
#pragma unroll
        for (int mb = 0; mb < 4; mb++)
#pragma unroll
            for (int hf = 0; hf < 2; hf++) {
                const int n = n0 + wm * 64 + mb * 16 + (lane >> 2) + hf * 8;
                float2 v = make_float2(acc[mb][nb][hf * 2] + b0,
                                       acc[mb][nb][hf * 2 + 1] + b1);
                *(float2*)(out + (size_t)n * (SS * MM) + s * MM + mc) = v;
            }
    }
}

// ---------------------------------------------------------------------------
// Launch. Inputs: modulation, Wxi, Whi, bi, Wxf, Whf, bf, Wxg, Whg, bg,
// Wxo, Who, bo, Wout, bout. h0 = c0 = 0 kills Whi/Wxf/Whf/bf/Whg/Who.
// ---------------------------------------------------------------------------
extern "C" void kernel_launch(void* const* d_in, const int* in_sizes, int n_in,
                              void* d_out, int out_size) {
    const float* mod  = (const float*)d_in[0];
    const float* Wxi  = (const float*)d_in[1];
    const float* bi   = (const float*)d_in[3];
    const float* Wxg  = (const float*)d_in[7];
    const float* bg   = (const float*)d_in[9];
    const float* Wxo  = (const float*)d_in[10];
    const float* bo   = (const float*)d_in[12];
    const float* Wout = (const float*)d_in[13];
    const float* bout = (const float*)d_in[14];
    float* out = (float*)d_out;

    cudaFuncSetAttribute(gates_mma, cudaFuncAttributeMaxDynamicSharedMemorySize, 87040);
    cudaFuncSetAttribute(out_mma,   cudaFuncAttributeMaxDynamicSharedMemorySize, 81920);

    convert_xw<<<4096, 256>>>(mod, Wxi, Wxg, Wxo);

    // 1024 gates blocks + 512 Wout-convert blocks in one launch
    gates_mma<<<1536, 512, 87040>>>(bi, bg, bo, Wout);

    dim3 gOut(NN / 128, MM / 128, SS);    // (8, 4, 8)
    out_mma<<<gOut, 256, 81920>>>(bout, out);
}

// round 11
// speedup vs baseline: 1.5213x; 1.0004x over previous
#include <cuda_runtime.h>
#include <cuda_fp16.h>
#include <cstdint>
#include <math.h>

#define NN 1024
#define SS 8
#define II 128
#define FF 1024
#define MM 512

// ---------------------------------------------------------------------------
// Scratch (device globals). Pure fp16, single term.
// ---------------------------------------------------------------------------
__device__ __align__(16) __half g_xh[SS * NN * II];
__device__ __align__(16) __half g_wih[SS * FF * II];
__device__ __align__(16) __half g_wgh[SS * FF * II];
__device__ __align__(16) __half g_woh[SS * FF * II];
__device__ __align__(16) __half g_wouth[SS * MM * FF];
__device__ __align__(16) __half g_hh[SS * NN * FF];

// ---------------------------------------------------------------------------
// Helpers
// ---------------------------------------------------------------------------
__device__ __forceinline__ uint32_t smem_u32(const void* p) {
    uint32_t a;
    asm("{ .reg .u64 t; cvta.to.shared.u64 t, %1; cvt.u32.u64 %0, t; }"
        : "=r"(a) : "l"(p));
    return a;
}

__device__ __forceinline__ void ldsm4(uint32_t* r, uint32_t a) {
    asm volatile("ldmatrix.sync.aligned.m8n8.x4.shared.b16 {%0,%1,%2,%3}, [%4];"
        : "=r"(r[0]), "=r"(r[1]), "=r"(r[2]), "=r"(r[3]) : "r"(a));
}

__device__ __forceinline__ void mma_f16(float* d, const uint32_t* a,
                                        uint32_t b0, uint32_t b1) {
    asm volatile(
        "mma.sync.aligned.m16n8k16.row.col.f32.f16.f16.f32 "
        "{%0,%1,%2,%3}, {%4,%5,%6,%7}, {%8,%9}, {%0,%1,%2,%3};"
        : "+f"(d[0]), "+f"(d[1]), "+f"(d[2]), "+f"(d[3])
        : "r"(a[0]), "r"(a[1]), "r"(a[2]), "r"(a[3]), "r"(b0), "r"(b1));
}

__device__ __forceinline__ void cpasync16(uint32_t dst, const void* src) {
    asm volatile("cp.async.cg.shared.global [%0], [%1], 16;"
        :: "r"(dst), "l"(src));
}
#define CP_COMMIT() asm volatile("cp.async.commit_group;" ::: "memory")
#define CP_WAIT(n)  asm volatile("cp.async.wait_group %0;" :: "n"(n) : "memory")

// fp32 fast nonlinearities (MUFU EX2 + RCP; ~2 ulp — NOT the f16 approx path)
__device__ __forceinline__ float sigm_fast(float x) {
    return __fdividef(1.f, 1.f + __expf(-x));
}
__device__ __forceinline__ float tanh_fast(float x) {
    return __fdividef(2.f, 1.f + __expf(-2.f * x)) - 1.f;
}

// ---------------------------------------------------------------------------
// convert_xw: fp32 -> fp16 for x (remapped [N][S][I] -> [S][N][I]) and the
// three gate weights. 1,048,576 float4 items, grid 4096 x 256.
// ---------------------------------------------------------------------------
__global__ __launch_bounds__(256) void convert_xw(
    const float* __restrict__ mod, const float* __restrict__ Wxi,
    const float* __restrict__ Wxg, const float* __restrict__ Wxo)
{
    const int i = blockIdx.x * 256 + threadIdx.x;
    if (i < 262144) {                       // x remap
        int i4 = i & 31, n = (i >> 5) & 1023, s = i >> 15;
        float4 v = *(const float4*)(mod + (size_t)n * (SS * II) + s * II + i4 * 4);
        __half h[4] = {__float2half_rn(v.x), __float2half_rn(v.y),
                       __float2half_rn(v.z), __float2half_rn(v.w)};
        *(uint2*)(g_xh + ((size_t)s * NN + n) * II + i4 * 4) = *(uint2*)h;
        return;
    }
    const float* src;
    __half* dh;
    size_t j;
    if (i < 524288)      { j = (size_t)(i - 262144) * 4; src = Wxi; dh = g_wih; }
    else if (i < 786432) { j = (size_t)(i - 524288) * 4; src = Wxg; dh = g_wgh; }
    else                 { j = (size_t)(i - 786432) * 4; src = Wxo; dh = g_woh; }

    float4 v = *(const float4*)(src + j);
    __half h[4] = {__float2half_rn(v.x), __float2half_rn(v.y),
                   __float2half_rn(v.z), __float2half_rn(v.w)};
    *(uint2*)(dh + j) = *(uint2*)h;
}

// ---------------------------------------------------------------------------
// Gates kernel + Wout conversion piggyback.
// Blocks [0,1024): CTA tile 128(n) x 64(f), all 3 gates, K=128 resident.
//   512 threads = 16 warps (4x4), warp tile 32(n) x 16(f). Single-term fp16.
//   Fused LSTM epilogue (fp32 MUFU fast-math) -> h fp16. smem 87040 B.
// Blocks [1024,1536): convert Wout fp32 -> g_wouth fp16 (overlaps with the
//   HMMA-bound gates blocks).
// grid 1536 x 512.
// ---------------------------------------------------------------------------
__global__ __launch_bounds__(512, 1) void gates_mma(
    const float* __restrict__ bi, const float* __restrict__ bg,
    const float* __restrict__ bo, const float* __restrict__ Wout)
{
    const int bx = blockIdx.x;
    const int tid = threadIdx.x;

    if (bx >= 1024) {                       // ---- Wout conversion blocks ----
        const int cb = bx - 1024;           // 0..511, 2048 float4 each
        const float4* src = (const float4*)Wout;
#pragma unroll
        for (int it = 0; it < 4; it++) {
            size_t j = (size_t)cb * 2048 + it * 512 + tid;
            float4 v = src[j];
            __half h[4] = {__float2half_rn(v.x), __float2half_rn(v.y),
                           __float2half_rn(v.z), __float2half_rn(v.w)};
            *(uint2*)(g_wouth + j * 4) = *(uint2*)h;
        }
        return;
    }

    extern __shared__ __half sm[];
    constexpr int PAD = 136;                 // k-stride (fp16): 272 B, ldsm-clean
    constexpr uint32_t OFF_B = 128 * PAD;    // A[128][PAD], then per-gate B[64][PAD]
    const int wid = tid >> 5, lane = tid & 31;
    const int s = bx >> 7, f0 = ((bx >> 3) & 15) * 64, n0 = (bx & 7) * 128;
    const uint32_t sb = smem_u32(sm);

    // ---- one-shot cp.async fill ----
    {
        const __half* sa = g_xh + ((size_t)s * NN + n0) * II;
#pragma unroll
        for (int it = 0; it < 4; it++) {
            int idx = tid + it * 512;
            int row = idx >> 4, q = idx & 15;
            cpasync16(sb + 2 * (row * PAD + q * 8), sa + (size_t)row * II + q * 8);
        }
        const __half* WH[3] = {g_wih, g_wgh, g_woh};
#pragma unroll
        for (int g = 0; g < 3; g++) {
            const __half* bh = WH[g] + ((size_t)s * FF + f0) * II;
            uint32_t dh = OFF_B + g * 64 * PAD;
#pragma unroll
            for (int it = 0; it < 2; it++) {
                int idx = tid + it * 512;
                int row = idx >> 4, q = idx & 15;
                cpasync16(sb + 2 * (dh + row * PAD + q * 8),
                          bh + (size_t)row * II + q * 8);
            }
        }
    }
    CP_COMMIT();
    CP_WAIT(0);
    __syncthreads();

    const int wm = wid & 3, wn = wid >> 2;
    const int lrA = lane & 15, lcA = (lane >> 4) << 3;
    const int lrB = ((lane >> 4) << 3) + (lane & 7), lcB = ((lane >> 3) & 1) << 3;

    float acc[3][2][2][4];
#pragma unroll
    for (int g = 0; g < 3; g++)
#pragma unroll
        for (int mb = 0; mb < 2; mb++)
#pragma unroll
            for (int nb = 0; nb < 2; nb++)
#pragma unroll
                for (int e = 0; e < 4; e++) acc[g][mb][nb][e] = 0.f;

    const uint32_t aAh = sb + 2 * ((wm * 32 + lrA) * PAD + lcA);

#pragma unroll
    for (int kk = 0; kk < 8; kk++) {
        const int k0 = kk * 16;
        uint32_t ah[2][4];
        ldsm4(ah[0], aAh + 2 * k0);
        ldsm4(ah[1], aAh + 2 * (16 * PAD + k0));
#pragma unroll
        for (int g = 0; g < 3; g++) {
            const uint32_t bgb = sb + 2 * (OFF_B + g * 64 * PAD
                                 + (wn * 16 + lrB) * PAD + k0 + lcB);
            uint32_t bh[4];
            ldsm4(bh, bgb);
#pragma unroll
            for (int mb = 0; mb < 2; mb++)
#pragma unroll
                for (int nb = 0; nb < 2; nb++)
                    mma_f16(acc[g][mb][nb], ah[mb], bh[nb * 2], bh[nb * 2 + 1]);
        }
    }

    // ---- fused LSTM epilogue (fp32): h = sigm(o)*tanh(sigm(i)*tanh(g)) ----
#pragma unroll
    for (int nb = 0; nb < 2; nb++) {
        const int fc = f0 + wn * 16 + nb * 8 + (lane & 3) * 2;
        const float bi0 = bi[(size_t)s * FF + fc], bi1 = bi[(size_t)s * FF + fc + 1];
        const float bg0 = bg[(size_t)s * FF + fc], bg1 = bg[(size_t)s * FF + fc + 1];
        const float bo0 = bo[(size_t)s * FF + fc], bo1 = bo[(size_t)s * FF + fc + 1];
#pragma unroll
        for (int mb = 0; mb < 2; mb++)
#pragma unroll
            for (int hf = 0; hf < 2; hf++) {
                const int n = n0 + wm * 32 + mb * 16 + (lane >> 2) + hf * 8;
                const size_t off = ((size_t)s * NN + n) * FF + fc;
                float h2[2];
#pragma unroll
                for (int e = 0; e < 2; e++) {
                    float pi = acc[0][mb][nb][hf * 2 + e] + (e ? bi1 : bi0);
                    float pg = acc[1][mb][nb][hf * 2 + e] + (e ? bg1 : bg0);
                    float po = acc[2][mb][nb][hf * 2 + e] + (e ? bo1 : bo0);
                    float cv = sigm_fast(pi) * tanh_fast(pg);
                    h2[e] = sigm_fast(po) * tanh_fast(cv);
                }
                *(__half2*)(g_hh + off) = __floats2half2_rn(h2[0], h2[1]);
            }
    }
}

// ---------------------------------------------------------------------------
// Out kernel: CTA tile 128(n) x 128(m). 256 threads = 8 warps (2x4),
// warp tile 64(n) x 32(m). K=1024 in 32 chunks of 32, 4-stage cp.async
// pipeline with ONE sync per iteration. 2 CTAs/SM (smem 81920 B).
// grid (8, 4, 8) -> single wave at 2/SM.
// ---------------------------------------------------------------------------
__global__ __launch_bounds__(256, 2) void out_mma(
    const float* __restrict__ bout, float* __restrict__ out)
{
    extern __shared__ __half sm[];
    constexpr int PB = 40;                         // row stride (80 B, ldsm-clean)
    constexpr uint32_t TEN = 128 * PB;             // elems per tensor per stage
    constexpr uint32_t STG_B = 2u * TEN * 2;       // 20480 B per stage, 4 stages

    const int tid = threadIdx.x, wid = tid >> 5, lane = tid & 31;
    const int s = blockIdx.z, n0 = blockIdx.x * 128, m0 = blockIdx.y * 128;
    const uint32_t sb = smem_u32(sm);

    const __half* gA = g_hh    + ((size_t)s * NN + n0) * FF;
    const __half* gB = g_wouth + ((size_t)s * MM + m0) * FF;

    auto load = [&](int ch, int stg) {
        const int kc = ch * 32;
        const uint32_t base = sb + (uint32_t)stg * STG_B;
#pragma unroll
        for (int it = 0; it < 2; it++) {
            int idx = tid + it * 256;
            int row = idx >> 2, q = idx & 3;
            const uint32_t d = 2 * (row * PB + q * 8);
            const size_t so = (size_t)row * FF + kc + q * 8;
            cpasync16(base + d,           gA + so);
            cpasync16(base + 2 * TEN + d, gB + so);
        }
    };

    const int wm = wid & 1, wn = wid >> 1;
    const int lrA = lane & 15, lcA = (lane >> 4) << 3;
    const int lrB = ((lane >> 4) << 3) + (lane & 7), lcB = ((lane >> 3) & 1) << 3;

    float acc[4][4][4];
#pragma unroll
    for (int mb = 0; mb < 4; mb++)
#pragma unroll
        for (int nb = 0; nb < 4; nb++)
#pragma unroll
            for (int e = 0; e < 4; e++) acc[mb][nb][e] = 0.f;

    load(0, 0); CP_COMMIT();
    load(1, 1); CP_COMMIT();
    load(2, 2); CP_COMMIT();

#pragma unroll 1
    for (int ch = 0; ch < 32; ch++) {
        CP_WAIT(2);
        __syncthreads();
        // sync above also guarantees stage (ch+3)&3 (consumed at ch-1) is free
        if (ch + 3 < 32) load(ch + 3, (ch + 3) & 3);
        CP_COMMIT();

        const int stg = ch & 3;
        const uint32_t base = sb + (uint32_t)stg * STG_B;
        const uint32_t aA = base + 2 * ((wm * 64 + lrA) * PB + lcA);
        const uint32_t aB = base + 2 * (TEN + (wn * 32 + lrB) * PB + lcB);

#pragma unroll
        for (int kk = 0; kk < 2; kk++) {
            const int k0 = kk * 16;
            uint32_t ah[4][4], bh[2][4];
#pragma unroll
            for (int mb = 0; mb < 4; mb++)
                ldsm4(ah[mb], aA + 2 * (mb * 16 * PB + k0));
#pragma unroll
            for (int p = 0; p < 2; p++)
                ldsm4(bh[p], aB + 2 * (p * 16 * PB + k0));
#pragma unroll
            for (int mb = 0; mb < 4; mb++)
#pragma unroll
                for (int nb = 0; nb < 4; nb++)
                    mma_f16(acc[mb][nb], ah[mb],
                            bh[nb >> 1][(nb & 1) * 2], bh[nb >> 1][(nb & 1) * 2 + 1]);
        }
    }

    // ---- epilogue: bias + fp32 store ----
#pragma unroll
    for (int nb = 0; nb < 4; nb++) {
        const int mc = m0 + wn * 32 + nb * 8 + (lane & 3) * 2;
        const float b0 = bout[(size_t)s * MM + mc];
        const float b1 = bout[(size_t)s * MM + mc + 1];
#pragma unroll
        for (int mb = 0; mb < 4; mb++)
#pragma unroll
            for (int hf = 0; hf < 2; hf++) {
                const int n = n0 + wm * 64 + mb * 16 + (lane >> 2) + hf * 8;
                float2 v = make_float2(acc[mb][nb][hf * 2] + b0,
                                       acc[mb][nb][hf * 2 + 1] + b1);
                *(float2*)(out + (size_t)n * (SS * MM) + s * MM + mc) = v;
            }
    }
}

// ---------------------------------------------------------------------------
// Launch. Inputs: modulation, Wxi, Whi, bi, Wxf, Whf, bf, Wxg, Whg, bg,
// Wxo, Who, bo, Wout, bout. h0 = c0 = 0 kills Whi/Wxf/Whf/bf/Whg/Who.
// ---------------------------------------------------------------------------
extern "C" void kernel_launch(void* const* d_in, const int* in_sizes, int n_in,
                              void* d_out, int out_size) {
    const float* mod  = (const float*)d_in[0];
    const float* Wxi  = (const float*)d_in[1];
    const float* bi   = (const float*)d_in[3];
    const float* Wxg  = (const float*)d_in[7];
    const float* bg   = (const float*)d_in[9];
    const float* Wxo  = (const float*)d_in[10];
    const float* bo   = (const float*)d_in[12];
    const float* Wout = (const float*)d_in[13];
    const float* bout = (const float*)d_in[14];
    float* out = (float*)d_out;

    cudaFuncSetAttribute(gates_mma, cudaFuncAttributeMaxDynamicSharedMemorySize, 87040);
    cudaFuncSetAttribute(out_mma,   cudaFuncAttributeMaxDynamicSharedMemorySize, 81920);

    convert_xw<<<4096, 256>>>(mod, Wxi, Wxg, Wxo);

    // 1024 gates blocks + 512 Wout-convert blocks in one launch
    gates_mma<<<1536, 512, 87040>>>(bi, bg, bo, Wout);

    dim3 gOut(NN / 128, MM / 128, SS);    // (8, 4, 8)
    out_mma<<<gOut, 256, 81920>>>(bout, out);
}

// round 12
// speedup vs baseline: 1.6382x; 1.0769x over previous
#include <cuda_runtime.h>
#include <cuda_fp16.h>
#include <cstdint>
#include <math.h>

#define NN 1024
#define SS 8
#define II 128
#define FF 1024
#define MM 512

// ---------------------------------------------------------------------------
// Scratch (device globals). Pure fp16, single term.
// ---------------------------------------------------------------------------
__device__ __align__(16) __half g_xh[SS * NN * II];
__device__ __align__(16) __half g_wih[SS * FF * II];
__device__ __align__(16) __half g_wgh[SS * FF * II];
__device__ __align__(16) __half g_woh[SS * FF * II];
__device__ __align__(16) __half g_wouth[SS * MM * FF];
__device__ __align__(16) __half g_hh[SS * NN * FF];

// ---------------------------------------------------------------------------
// Helpers
// ---------------------------------------------------------------------------
__device__ __forceinline__ uint32_t smem_u32(const void* p) {
    uint32_t a;
    asm("{ .reg .u64 t; cvta.to.shared.u64 t, %1; cvt.u32.u64 %0, t; }"
        : "=r"(a) : "l"(p));
    return a;
}

__device__ __forceinline__ void ldsm4(uint32_t* r, uint32_t a) {
    asm volatile("ldmatrix.sync.aligned.m8n8.x4.shared.b16 {%0,%1,%2,%3}, [%4];"
        : "=r"(r[0]), "=r"(r[1]), "=r"(r[2]), "=r"(r[3]) : "r"(a));
}

__device__ __forceinline__ void mma_f16(float* d, const uint32_t* a,
                                        uint32_t b0, uint32_t b1) {
    asm volatile(
        "mma.sync.aligned.m16n8k16.row.col.f32.f16.f16.f32 "
        "{%0,%1,%2,%3}, {%4,%5,%6,%7}, {%8,%9}, {%0,%1,%2,%3};"
        : "+f"(d[0]), "+f"(d[1]), "+f"(d[2]), "+f"(d[3])
        : "r"(a[0]), "r"(a[1]), "r"(a[2]), "r"(a[3]), "r"(b0), "r"(b1));
}

__device__ __forceinline__ void cpasync16(uint32_t dst, const void* src) {
    asm volatile("cp.async.cg.shared.global [%0], [%1], 16;"
        :: "r"(dst), "l"(src));
}
#define CP_COMMIT() asm volatile("cp.async.commit_group;" ::: "memory")
#define CP_WAIT(n)  asm volatile("cp.async.wait_group %0;" :: "n"(n) : "memory")

// fp32 fast nonlinearities (MUFU EX2 + RCP; ~2 ulp)
__device__ __forceinline__ float sigm_fast(float x) {
    return __fdividef(1.f, 1.f + __expf(-x));
}
__device__ __forceinline__ float tanh_fast(float x) {
    return __fdividef(2.f, 1.f + __expf(-2.f * x)) - 1.f;
}

// ---------------------------------------------------------------------------
// convert_all: fp32 -> fp16 for x (remapped [N][S][I] -> [S][N][I]), the
// three gate weights, and Wout. 2,097,152 float4 items, grid 8192 x 256.
// ---------------------------------------------------------------------------
__global__ __launch_bounds__(256) void convert_all(
    const float* __restrict__ mod, const float* __restrict__ Wxi,
    const float* __restrict__ Wxg, const float* __restrict__ Wxo,
    const float* __restrict__ Wout)
{
    const int i = blockIdx.x * 256 + threadIdx.x;
    if (i < 262144) {                       // x remap
        int i4 = i & 31, n = (i >> 5) & 1023, s = i >> 15;
        float4 v = *(const float4*)(mod + (size_t)n * (SS * II) + s * II + i4 * 4);
        __half h[4] = {__float2half_rn(v.x), __float2half_rn(v.y),
                       __float2half_rn(v.z), __float2half_rn(v.w)};
        *(uint2*)(g_xh + ((size_t)s * NN + n) * II + i4 * 4) = *(uint2*)h;
        return;
    }
    const float* src;
    __half* dh;
    size_t j;
    if (i < 524288)       { j = (size_t)(i - 262144) * 4;  src = Wxi;  dh = g_wih; }
    else if (i < 786432)  { j = (size_t)(i - 524288) * 4;  src = Wxg;  dh = g_wgh; }
    else if (i < 1048576) { j = (size_t)(i - 786432) * 4;  src = Wxo;  dh = g_woh; }
    else                  { j = (size_t)(i - 1048576) * 4; src = Wout; dh = g_wouth; }

    float4 v = *(const float4*)(src + j);
    __half h[4] = {__float2half_rn(v.x), __float2half_rn(v.y),
                   __float2half_rn(v.z), __float2half_rn(v.w)};
    *(uint2*)(dh + j) = *(uint2*)h;
}

// ---------------------------------------------------------------------------
// PERSISTENT gates kernel: 148 CTAs, each processes ~7 of the 1024 tiles
// (tile = 128 n x 64 f x one stream, all 3 gates, K=128).
// Two 87040 B smem stages, double-buffered via cp.async: prefetch tile i+1
// while computing tile i -> fill latency exposed only once per CTA, no wave
// transitions. 512 threads = 16 warps (4x4), warp tile 32(n) x 16(f).
// Fused LSTM epilogue -> h fp16. smem 174080 B.
// ---------------------------------------------------------------------------
__global__ __launch_bounds__(512, 1) void gates_mma(
    const float* __restrict__ bi, const float* __restrict__ bg,
    const float* __restrict__ bo)
{
    extern __shared__ __half sm[];
    constexpr int PAD = 136;                     // k-stride (fp16), ldsm-clean
    constexpr uint32_t OFF_B = 128 * PAD;        // A[128][PAD] then 3x B[64][PAD]
    constexpr uint32_t STAGE_E = 128 * PAD + 3 * 64 * PAD;  // 43520 halves

    const int bx = blockIdx.x;                   // 0..147
    const int tid = threadIdx.x, wid = tid >> 5, lane = tid & 31;
    const uint32_t sb = smem_u32(sm);

    const __half* WH[3] = {g_wih, g_wgh, g_woh};

    // issue cp.async fill of tile t into stage at element offset st
    auto fill = [&](int t, uint32_t st) {
        const int s = t >> 7, f0 = ((t >> 3) & 15) * 64, n0 = (t & 7) * 128;
        const __half* sa = g_xh + ((size_t)s * NN + n0) * II;
#pragma unroll
        for (int it = 0; it < 4; it++) {
            int idx = tid + it * 512;
            int row = idx >> 4, q = idx & 15;
            cpasync16(sb + 2 * (st + row * PAD + q * 8),
                      sa + (size_t)row * II + q * 8);
        }
#pragma unroll
        for (int g = 0; g < 3; g++) {
            const __half* bh = WH[g] + ((size_t)s * FF + f0) * II;
            uint32_t dh = st + OFF_B + g * 64 * PAD;
#pragma unroll
            for (int it = 0; it < 2; it++) {
                int idx = tid + it * 512;
                int row = idx >> 4, q = idx & 15;
                cpasync16(sb + 2 * (dh + row * PAD + q * 8),
                          bh + (size_t)row * II + q * 8);
            }
        }
    };

    const int wm = wid & 3, wn = wid >> 2;
    const int lrA = lane & 15, lcA = (lane >> 4) << 3;
    const int lrB = ((lane >> 4) << 3) + (lane & 7), lcB = ((lane >> 3) & 1) << 3;

    fill(bx, 0);
    CP_COMMIT();

    int stage = 0;
#pragma unroll 1
    for (int t = bx; t < 1024; t += 148) {
        // prefetch next tile into the other stage (freed by last iter's sync)
        const int tn = t + 148;
        if (tn < 1024) fill(tn, (uint32_t)(stage ^ 1) * STAGE_E);
        CP_COMMIT();
        CP_WAIT(1);                 // current tile's group complete
        __syncthreads();

        const uint32_t st = (uint32_t)stage * STAGE_E;
        const int s = t >> 7, f0 = ((t >> 3) & 15) * 64, n0 = (t & 7) * 128;

        float acc[3][2][2][4];
#pragma unroll
        for (int g = 0; g < 3; g++)
#pragma unroll
            for (int mb = 0; mb < 2; mb++)
#pragma unroll
                for (int nb = 0; nb < 2; nb++)
#pragma unroll
                    for (int e = 0; e < 4; e++) acc[g][mb][nb][e] = 0.f;

        const uint32_t aAh = sb + 2 * (st + (wm * 32 + lrA) * PAD + lcA);

#pragma unroll
        for (int kk = 0; kk < 8; kk++) {
            const int k0 = kk * 16;
            uint32_t ah[2][4];
            ldsm4(ah[0], aAh + 2 * k0);
            ldsm4(ah[1], aAh + 2 * (16 * PAD + k0));
#pragma unroll
            for (int g = 0; g < 3; g++) {
                const uint32_t bgb = sb + 2 * (st + OFF_B + g * 64 * PAD
                                     + (wn * 16 + lrB) * PAD + k0 + lcB);
                uint32_t bh[4];
                ldsm4(bh, bgb);
#pragma unroll
                for (int mb = 0; mb < 2; mb++)
#pragma unroll
                    for (int nb = 0; nb < 2; nb++)
                        mma_f16(acc[g][mb][nb], ah[mb], bh[nb * 2], bh[nb * 2 + 1]);
            }
        }

        // ---- fused LSTM epilogue: h = sigm(o)*tanh(sigm(i)*tanh(g)) ----
#pragma unroll
        for (int nb = 0; nb < 2; nb++) {
            const int fc = f0 + wn * 16 + nb * 8 + (lane & 3) * 2;
            const float bi0 = bi[(size_t)s * FF + fc], bi1 = bi[(size_t)s * FF + fc + 1];
            const float bg0 = bg[(size_t)s * FF + fc], bg1 = bg[(size_t)s * FF + fc + 1];
            const float bo0 = bo[(size_t)s * FF + fc], bo1 = bo[(size_t)s * FF + fc + 1];
#pragma unroll
            for (int mb = 0; mb < 2; mb++)
#pragma unroll
                for (int hf = 0; hf < 2; hf++) {
                    const int n = n0 + wm * 32 + mb * 16 + (lane >> 2) + hf * 8;
                    const size_t off = ((size_t)s * NN + n) * FF + fc;
                    float h2[2];
#pragma unroll
                    for (int e = 0; e < 2; e++) {
                        float pi = acc[0][mb][nb][hf * 2 + e] + (e ? bi1 : bi0);
                        float pg = acc[1][mb][nb][hf * 2 + e] + (e ? bg1 : bg0);
                        float po = acc[2][mb][nb][hf * 2 + e] + (e ? bo1 : bo0);
                        float cv = sigm_fast(pi) * tanh_fast(pg);
                        h2[e] = sigm_fast(po) * tanh_fast(cv);
                    }
                    *(__half2*)(g_hh + off) = __floats2half2_rn(h2[0], h2[1]);
                }
        }
        __syncthreads();            // all reads of this stage done -> reusable
        stage ^= 1;
    }
}

// ---------------------------------------------------------------------------
// Out kernel: CTA tile 128(n) x 128(m). 256 threads = 8 warps (2x4),
// warp tile 64(n) x 32(m). K=1024 in 32 chunks of 32, 4-stage cp.async
// pipeline with ONE sync per iteration. 2 CTAs/SM (smem 81920 B).
// grid (8, 4, 8) -> single wave at 2/SM.
// ---------------------------------------------------------------------------
__global__ __launch_bounds__(256, 2) void out_mma(
    const float* __restrict__ bout, float* __restrict__ out)
{
    extern __shared__ __half sm[];
    constexpr int PB = 40;                         // row stride (80 B, ldsm-clean)
    constexpr uint32_t TEN = 128 * PB;             // elems per tensor per stage
    constexpr uint32_t STG_B = 2u * TEN * 2;       // 20480 B per stage, 4 stages

    const int tid = threadIdx.x, wid = tid >> 5, lane = tid & 31;
    const int s = blockIdx.z, n0 = blockIdx.x * 128, m0 = blockIdx.y * 128;
    const uint32_t sb = smem_u32(sm);

    const __half* gA = g_hh    + ((size_t)s * NN + n0) * FF;
    const __half* gB = g_wouth + ((size_t)s * MM + m0) * FF;

    auto load = [&](int ch, int stg) {
        const int kc = ch * 32;
        const uint32_t base = sb + (uint32_t)stg * STG_B;
#pragma unroll
        for (int it = 0; it < 2; it++) {
            int idx = tid + it * 256;
            int row = idx >> 2, q = idx & 3;
            const uint32_t d = 2 * (row * PB + q * 8);
            const size_t so = (size_t)row * FF + kc + q * 8;
            cpasync16(base + d,           gA + so);
            cpasync16(base + 2 * TEN + d, gB + so);
        }
    };

    const int wm = wid & 1, wn = wid >> 1;
    const int lrA = lane & 15, lcA = (lane >> 4) << 3;
    const int lrB = ((lane >> 4) << 3) + (lane & 7), lcB = ((lane >> 3) & 1) << 3;

    float acc[4][4][4];
#pragma unroll
    for (int mb = 0; mb < 4; mb++)
#pragma unroll
        for (int nb = 0; nb < 4; nb++)
#pragma unroll
            for (int e = 0; e < 4; e++) acc[mb][nb][e] = 0.f;

    load(0, 0); CP_COMMIT();
    load(1, 1); CP_COMMIT();
    load(2, 2); CP_COMMIT();

#pragma unroll 1
    for (int ch = 0; ch < 32; ch++) {
        CP_WAIT(2);
        __syncthreads();
        // sync above also guarantees stage (ch+3)&3 (consumed at ch-1) is free
        if (ch + 3 < 32) load(ch + 3, (ch + 3) & 3);
        CP_COMMIT();

        const int stg = ch & 3;
        const uint32_t base = sb + (uint32_t)stg * STG_B;
        const uint32_t aA = base + 2 * ((wm * 64 + lrA) * PB + lcA);
        const uint32_t aB = base + 2 * (TEN + (wn * 32 + lrB) * PB + lcB);

#pragma unroll
        for (int kk = 0; kk < 2; kk++) {
            const int k0 = kk * 16;
            uint32_t ah[4][4], bh[2][4];
#pragma unroll
            for (int mb = 0; mb < 4; mb++)
                ldsm4(ah[mb], aA + 2 * (mb * 16 * PB + k0));
#pragma unroll
            for (int p = 0; p < 2; p++)
                ldsm4(bh[p], aB + 2 * (p * 16 * PB + k0));
#pragma unroll
            for (int mb = 0; mb < 4; mb++)
#pragma unroll
                for (int nb = 0; nb < 4; nb++)
                    mma_f16(acc[mb][nb], ah[mb],
                            bh[nb >> 1][(nb & 1) * 2], bh[nb >> 1][(nb & 1) * 2 + 1]);
        }
    }

    // ---- epilogue: bias + fp32 store ----
#pragma unroll
    for (int nb = 0; nb < 4; nb++) {
        const int mc = m0 + wn * 32 + nb * 8 + (lane & 3) * 2;
        const float b0 = bout[(size_t)s * MM + mc];
        const float b1 = bout[(size_t)s * MM + mc + 1];
#pragma unroll
        for (int mb = 0; mb < 4; mb++)
#pragma unroll
            for (int hf = 0; hf < 2; hf++) {
                const int n = n0 + wm * 64 + mb * 16 + (lane >> 2) + hf * 8;
                float2 v = make_float2(acc[mb][nb][hf * 2] + b0,
                                       acc[mb][nb][hf * 2 + 1] + b1);
                *(float2*)(out + (size_t)n * (SS * MM) + s * MM + mc) = v;
            }
    }
}

// ---------------------------------------------------------------------------
// Launch. Inputs: modulation, Wxi, Whi, bi, Wxf, Whf, bf, Wxg, Whg, bg,
// Wxo, Who, bo, Wout, bout. h0 = c0 = 0 kills Whi/Wxf/Whf/bf/Whg/Who.
// ---------------------------------------------------------------------------
extern "C" void kernel_launch(void* const* d_in, const int* in_sizes, int n_in,
                              void* d_out, int out_size) {
    const float* mod  = (const float*)d_in[0];
    const float* Wxi  = (const float*)d_in[1];
    const float* bi   = (const float*)d_in[3];
    const float* Wxg  = (const float*)d_in[7];
    const float* bg   = (const float*)d_in[9];
    const float* Wxo  = (const float*)d_in[10];
    const float* bo   = (const float*)d_in[12];
    const float* Wout = (const float*)d_in[13];
    const float* bout = (const float*)d_in[14];
    float* out = (float*)d_out;

    cudaFuncSetAttribute(gates_mma, cudaFuncAttributeMaxDynamicSharedMemorySize, 174080);
    cudaFuncSetAttribute(out_mma,   cudaFuncAttributeMaxDynamicSharedMemorySize, 81920);

    convert_all<<<8192, 256>>>(mod, Wxi, Wxg, Wxo, Wout);

    gates_mma<<<148, 512, 174080>>>(bi, bg, bo);   // persistent, 1 CTA/SM

    dim3 gOut(NN / 128, MM / 128, SS);             // (8, 4, 8)
    out_mma<<<gOut, 256, 81920>>>(bout, out);
}

// round 13
// speedup vs baseline: 1.7416x; 1.0631x over previous
#include <cuda_runtime.h>
#include <cuda_fp16.h>
#include <cstdint>
#include <math.h>

#define NN 1024
#define SS 8
#define II 128
#define FF 1024
#define MM 512

// ---------------------------------------------------------------------------
// Scratch (device globals). Pure fp16, single term.
// ---------------------------------------------------------------------------
__device__ __align__(16) __half g_xh[SS * NN * II];
__device__ __align__(16) __half g_wouth[SS * MM * FF];
__device__ __align__(16) __half g_hh[SS * NN * FF];

// ---------------------------------------------------------------------------
// Helpers
// ---------------------------------------------------------------------------
__device__ __forceinline__ uint32_t smem_u32(const void* p) {
    uint32_t a;
    asm("{ .reg .u64 t; cvta.to.shared.u64 t, %1; cvt.u32.u64 %0, t; }"
        : "=r"(a) : "l"(p));
    return a;
}

__device__ __forceinline__ void ldsm4(uint32_t* r, uint32_t a) {
    asm volatile("ldmatrix.sync.aligned.m8n8.x4.shared.b16 {%0,%1,%2,%3}, [%4];"
        : "=r"(r[0]), "=r"(r[1]), "=r"(r[2]), "=r"(r[3]) : "r"(a));
}

__device__ __forceinline__ void mma_f16(float* d, const uint32_t* a,
                                        uint32_t b0, uint32_t b1) {
    asm volatile(
        "mma.sync.aligned.m16n8k16.row.col.f32.f16.f16.f32 "
        "{%0,%1,%2,%3}, {%4,%5,%6,%7}, {%8,%9}, {%0,%1,%2,%3};"
        : "+f"(d[0]), "+f"(d[1]), "+f"(d[2]), "+f"(d[3])
        : "r"(a[0]), "r"(a[1]), "r"(a[2]), "r"(a[3]), "r"(b0), "r"(b1));
}

__device__ __forceinline__ void cpasync16(uint32_t dst, const void* src) {
    asm volatile("cp.async.cg.shared.global [%0], [%1], 16;"
        :: "r"(dst), "l"(src));
}
#define CP_COMMIT() asm volatile("cp.async.commit_group;" ::: "memory")
#define CP_WAIT(n)  asm volatile("cp.async.wait_group %0;" :: "n"(n) : "memory")

// fp32 fast nonlinearities (MUFU EX2 + RCP; ~2 ulp)
__device__ __forceinline__ float sigm_fast(float x) {
    return __fdividef(1.f, 1.f + __expf(-x));
}
__device__ __forceinline__ float tanh_fast(float x) {
    return __fdividef(2.f, 1.f + __expf(-2.f * x)) - 1.f;
}

// ---------------------------------------------------------------------------
// convert_xo: fp32 -> fp16 for x (remapped [N][S][I] -> [S][N][I]) and Wout.
// Gate weights are converted in-kernel by gates_mma (read once each).
// 1,310,720 float4 items, grid 5120 x 256.
// ---------------------------------------------------------------------------
__global__ __launch_bounds__(256) void convert_xo(
    const float* __restrict__ mod, const float* __restrict__ Wout)
{
    const int i = blockIdx.x * 256 + threadIdx.x;
    if (i < 262144) {                       // x remap
        int i4 = i & 31, n = (i >> 5) & 1023, s = i >> 15;
        float4 v = *(const float4*)(mod + (size_t)n * (SS * II) + s * II + i4 * 4);
        __half h[4] = {__float2half_rn(v.x), __float2half_rn(v.y),
                       __float2half_rn(v.z), __float2half_rn(v.w)};
        *(uint2*)(g_xh + ((size_t)s * NN + n) * II + i4 * 4) = *(uint2*)h;
        return;
    }
    size_t j = (size_t)(i - 262144) * 4;    // Wout
    float4 v = *(const float4*)(Wout + j);
    __half h[4] = {__float2half_rn(v.x), __float2half_rn(v.y),
                   __float2half_rn(v.z), __float2half_rn(v.w)};
    *(uint2*)(g_wouth + j) = *(uint2*)h;
}

// ---------------------------------------------------------------------------
// PERSISTENT weight-resident gates kernel: 128 CTAs, one per (s, f0) pair.
// Prologue: load the 3 gate-weight tiles (64f x 128k each) from fp32 global,
// convert to fp16, store to smem ONCE. Then loop over the 8 n-tiles with a
// double-buffered cp.async x fill (34816 B/stage). Warp tile 32(n) x 16(f),
// 512 threads = 16 warps (4x4). Fused LSTM epilogue -> h fp16.
// smem: 2 x-stages (34816 halves) + weights (26112 halves) = 121856 B.
// ---------------------------------------------------------------------------
__global__ __launch_bounds__(512, 1) void gates_mma(
    const float* __restrict__ bi, const float* __restrict__ bg,
    const float* __restrict__ bo,
    const float* __restrict__ Wxi, const float* __restrict__ Wxg,
    const float* __restrict__ Wxo)
{
    extern __shared__ __half sm[];
    constexpr int PAD = 136;                      // k-stride (halves), ldsm-clean
    constexpr uint32_t STAGE_E = 128 * PAD;       // x stage, 17408 halves
    constexpr uint32_t OFF_W = 2 * STAGE_E;       // weights: 3 x 64*PAD halves

    const int bx = blockIdx.x;                    // 0..127
    const int tid = threadIdx.x, wid = tid >> 5, lane = tid & 31;
    const int s = bx >> 4, f0 = (bx & 15) * 64;
    const uint32_t sb = smem_u32(sm);

    // ---- x-tile fill (cp.async): 128 rows x 128 halves ----
    auto fill_x = [&](int n0, uint32_t st) {
        const __half* sa = g_xh + ((size_t)s * NN + n0) * II;
#pragma unroll
        for (int it = 0; it < 4; it++) {
            int idx = tid + it * 512;
            int row = idx >> 4, q = idx & 15;
            cpasync16(sb + 2 * (st + row * PAD + q * 8),
                      sa + (size_t)row * II + q * 8);
        }
    };

    fill_x(0, 0);
    CP_COMMIT();

    // ---- weight prologue: fp32 LDG -> cvt -> STS (once per CTA) ----
    {
        const float* WS[3] = {Wxi, Wxg, Wxo};
#pragma unroll
        for (int g = 0; g < 3; g++) {
            const float* wsrc = WS[g] + ((size_t)s * FF + f0) * II;
#pragma unroll
            for (int it = 0; it < 4; it++) {
                int idx = tid + it * 512;          // 2048 float4 per gate
                int row = idx >> 5, q = idx & 31;  // 32 float4 per 128-k row
                float4 v = *(const float4*)(wsrc + (size_t)row * II + q * 4);
                __half h[4] = {__float2half_rn(v.x), __float2half_rn(v.y),
                               __float2half_rn(v.z), __float2half_rn(v.w)};
                *(uint2*)(sm + OFF_W + g * 64 * PAD + row * PAD + q * 4) =
                    *(uint2*)h;
            }
        }
    }

    const int wm = wid & 3, wn = wid >> 2;
    const int lrA = lane & 15, lcA = (lane >> 4) << 3;
    const int lrB = ((lane >> 4) << 3) + (lane & 7), lcB = ((lane >> 3) & 1) << 3;

    // biases: constant per CTA across the n-loop — load once
    const int fc0 = f0 + wn * 16 + (lane & 3) * 2;       // nb = 0
    const int fc1 = fc0 + 8;                             // nb = 1
    const float bia[4] = {bi[(size_t)s * FF + fc0], bi[(size_t)s * FF + fc0 + 1],
                          bi[(size_t)s * FF + fc1], bi[(size_t)s * FF + fc1 + 1]};
    const float bga[4] = {bg[(size_t)s * FF + fc0], bg[(size_t)s * FF + fc0 + 1],
                          bg[(size_t)s * FF + fc1], bg[(size_t)s * FF + fc1 + 1]};
    const float boa[4] = {bo[(size_t)s * FF + fc0], bo[(size_t)s * FF + fc0 + 1],
                          bo[(size_t)s * FF + fc1], bo[(size_t)s * FF + fc1 + 1]};

    int stage = 0;
#pragma unroll 1
    for (int i = 0; i < 8; i++) {
        const int n0 = i * 128;
        if (i + 1 < 8) fill_x(n0 + 128, (uint32_t)(stage ^ 1) * STAGE_E);
        CP_COMMIT();
        CP_WAIT(1);                 // current x stage complete
        __syncthreads();            // also orders the weight STS (first iter)

        const uint32_t st = (uint32_t)stage * STAGE_E;

        float acc[3][2][2][4];
#pragma unroll
        for (int g = 0; g < 3; g++)
#pragma unroll
            for (int mb = 0; mb < 2; mb++)
#pragma unroll
                for (int nb = 0; nb < 2; nb++)
#pragma unroll
                    for (int e = 0; e < 4; e++) acc[g][mb][nb][e] = 0.f;

        const uint32_t aAh = sb + 2 * (st + (wm * 32 + lrA) * PAD + lcA);

#pragma unroll
        for (int kk = 0; kk < 8; kk++) {
            const int k0 = kk * 16;
            uint32_t ah[2][4];
            ldsm4(ah[0], aAh + 2 * k0);
            ldsm4(ah[1], aAh + 2 * (16 * PAD + k0));
#pragma unroll
            for (int g = 0; g < 3; g++) {
                const uint32_t bgb = sb + 2 * (OFF_W + g * 64 * PAD
                                     + (wn * 16 + lrB) * PAD + k0 + lcB);
                uint32_t bh[4];
                ldsm4(bh, bgb);
#pragma unroll
                for (int mb = 0; mb < 2; mb++)
#pragma unroll
                    for (int nb = 0; nb < 2; nb++)
                        mma_f16(acc[g][mb][nb], ah[mb], bh[nb * 2], bh[nb * 2 + 1]);
            }
        }

        // ---- fused LSTM epilogue: h = sigm(o)*tanh(sigm(i)*tanh(g)) ----
#pragma unroll
        for (int nb = 0; nb < 2; nb++) {
            const int fc = (nb == 0) ? fc0 : fc1;
#pragma unroll
            for (int mb = 0; mb < 2; mb++)
#pragma unroll
                for (int hf = 0; hf < 2; hf++) {
                    const int n = n0 + wm * 32 + mb * 16 + (lane >> 2) + hf * 8;
                    const size_t off = ((size_t)s * NN + n) * FF + fc;
                    float h2[2];
#pragma unroll
                    for (int e = 0; e < 2; e++) {
                        float pi = acc[0][mb][nb][hf * 2 + e] + bia[nb * 2 + e];
                        float pg = acc[1][mb][nb][hf * 2 + e] + bga[nb * 2 + e];
                        float po = acc[2][mb][nb][hf * 2 + e] + boa[nb * 2 + e];
                        float cv = sigm_fast(pi) * tanh_fast(pg);
                        h2[e] = sigm_fast(po) * tanh_fast(cv);
                    }
                    *(__half2*)(g_hh + off) = __floats2half2_rn(h2[0], h2[1]);
                }
        }
        __syncthreads();            // all reads of this x stage done
        stage ^= 1;
    }
}

// ---------------------------------------------------------------------------
// Out kernel: CTA tile 128(n) x 128(m). 256 threads = 8 warps (2x4),
// warp tile 64(n) x 32(m). K=1024 in 32 chunks of 32, 4-stage cp.async
// pipeline with ONE sync per iteration. 2 CTAs/SM (smem 81920 B).
// grid (8, 4, 8) -> single wave at 2/SM.
// ---------------------------------------------------------------------------
__global__ __launch_bounds__(256, 2) void out_mma(
    const float* __restrict__ bout, float* __restrict__ out)
{
    extern __shared__ __half sm[];
    constexpr int PB = 40;                         // row stride (80 B, ldsm-clean)
    constexpr uint32_t TEN = 128 * PB;             // elems per tensor per stage
    constexpr uint32_t STG_B = 2u * TEN * 2;       // 20480 B per stage, 4 stages

    const int tid = threadIdx.x, wid = tid >> 5, lane = tid & 31;
    const int s = blockIdx.z, n0 = blockIdx.x * 128, m0 = blockIdx.y * 128;
    const uint32_t sb = smem_u32(sm);

    const __half* gA = g_hh    + ((size_t)s * NN + n0) * FF;
    const __half* gB = g_wouth + ((size_t)s * MM + m0) * FF;

    auto load = [&](int ch, int stg) {
        const int kc = ch * 32;
        const uint32_t base = sb + (uint32_t)stg * STG_B;
#pragma unroll
        for (int it = 0; it < 2; it++) {
            int idx = tid + it * 256;
            int row = idx >> 2, q = idx & 3;
            const uint32_t d = 2 * (row * PB + q * 8);
            const size_t so = (size_t)row * FF + kc + q * 8;
            cpasync16(base + d,           gA + so);
            cpasync16(base + 2 * TEN + d, gB + so);
        }
    };

    const int wm = wid & 1, wn = wid >> 1;
    const int lrA = lane & 15, lcA = (lane >> 4) << 3;
    const int lrB = ((lane >> 4) << 3) + (lane & 7), lcB = ((lane >> 3) & 1) << 3;

    float acc[4][4][4];
#pragma unroll
    for (int mb = 0; mb < 4; mb++)
#pragma unroll
        for (int nb = 0; nb < 4; nb++)
#pragma unroll
            for (int e = 0; e < 4; e++) acc[mb][nb][e] = 0.f;

    load(0, 0); CP_COMMIT();
    load(1, 1); CP_COMMIT();
    load(2, 2); CP_COMMIT();

#pragma unroll 1
    for (int ch = 0; ch < 32; ch++) {
        CP_WAIT(2);
        __syncthreads();
        // sync above also guarantees stage (ch+3)&3 (consumed at ch-1) is free
        if (ch + 3 < 32) load(ch + 3, (ch + 3) & 3);
        CP_COMMIT();

        const int stg = ch & 3;
        const uint32_t base = sb + (uint32_t)stg * STG_B;
        const uint32_t aA = base + 2 * ((wm * 64 + lrA) * PB + lcA);
        const uint32_t aB = base + 2 * (TEN + (wn * 32 + lrB) * PB + lcB);

#pragma unroll
        for (int kk = 0; kk < 2; kk++) {
            const int k0 = kk * 16;
            uint32_t ah[4][4], bh[2][4];
#pragma unroll
            for (int mb = 0; mb < 4; mb++)
                ldsm4(ah[mb], aA + 2 * (mb * 16 * PB + k0));
#pragma unroll
            for (int p = 0; p < 2; p++)
                ldsm4(bh[p], aB + 2 * (p * 16 * PB + k0));
#pragma unroll
            for (int mb = 0; mb < 4; mb++)
#pragma unroll
                for (int nb = 0; nb < 4; nb++)
                    mma_f16(acc[mb][nb], ah[mb],
                            bh[nb >> 1][(nb & 1) * 2], bh[nb >> 1][(nb & 1) * 2 + 1]);
        }
    }

    // ---- epilogue: bias + fp32 store ----
#pragma unroll
    for (int nb = 0; nb < 4; nb++) {
        const int mc = m0 + wn * 32 + nb * 8 + (lane & 3) * 2;
        const float b0 = bout[(size_t)s * MM + mc];
        const float b1 = bout[(size_t)s * MM + mc + 1];
#pragma unroll
        for (int mb = 0; mb < 4; mb++)
#pragma unroll
            for (int hf = 0; hf < 2; hf++) {
                const int n = n0 + wm * 64 + mb * 16 + (lane >> 2) + hf * 8;
                float2 v = make_float2(acc[mb][nb][hf * 2] + b0,
                                       acc[mb][nb][hf * 2 + 1] + b1);
                *(float2*)(out + (size_t)n * (SS * MM) + s * MM + mc) = v;
            }
    }
}

// ---------------------------------------------------------------------------
// Launch. Inputs: modulation, Wxi, Whi, bi, Wxf, Whf, bf, Wxg, Whg, bg,
// Wxo, Who, bo, Wout, bout. h0 = c0 = 0 kills Whi/Wxf/Whf/bf/Whg/Who.
// ---------------------------------------------------------------------------
extern "C" void kernel_launch(void* const* d_in, const int* in_sizes, int n_in,
                              void* d_out, int out_size) {
    const float* mod  = (const float*)d_in[0];
    const float* Wxi  = (const float*)d_in[1];
    const float* bi   = (const float*)d_in[3];
    const float* Wxg  = (const float*)d_in[7];
    const float* bg   = (const float*)d_in[9];
    const float* Wxo  = (const float*)d_in[10];
    const float* bo   = (const float*)d_in[12];
    const float* Wout = (const float*)d_in[13];
    const float* bout = (const float*)d_in[14];
    float* out = (float*)d_out;

    cudaFuncSetAttribute(gates_mma, cudaFuncAttributeMaxDynamicSharedMemorySize, 121856);
    cudaFuncSetAttribute(out_mma,   cudaFuncAttributeMaxDynamicSharedMemorySize, 81920);

    convert_xo<<<5120, 256>>>(mod, Wout);

    gates_mma<<<128, 512, 121856>>>(bi, bg, bo, Wxi, Wxg, Wxo);  // persistent

    dim3 gOut(NN / 128, MM / 128, SS);             // (8, 4, 8)
    out_mma<<<gOut, 256, 81920>>>(bout, out);
}

// round 14
// speedup vs baseline: 1.7709x; 1.0168x over previous
#include <cuda_runtime.h>
#include <cuda_fp16.h>
#include <cstdint>
#include <math.h>

#define NN 1024
#define SS 8
#define II 128
#define FF 1024
#define MM 512

// ---------------------------------------------------------------------------
// Scratch (device globals). Pure fp16, single term.
// ---------------------------------------------------------------------------
__device__ __align__(16) __half g_xh[SS * NN * II];
__device__ __align__(16) __half g_wouth[SS * MM * FF];
__device__ __align__(16) __half g_hh[SS * NN * FF];

// ---------------------------------------------------------------------------
// Helpers
// ---------------------------------------------------------------------------
__device__ __forceinline__ uint32_t smem_u32(const void* p) {
    uint32_t a;
    asm("{ .reg .u64 t; cvta.to.shared.u64 t, %1; cvt.u32.u64 %0, t; }"
        : "=r"(a) : "l"(p));
    return a;
}

__device__ __forceinline__ void ldsm4(uint32_t* r, uint32_t a) {
    asm volatile("ldmatrix.sync.aligned.m8n8.x4.shared.b16 {%0,%1,%2,%3}, [%4];"
        : "=r"(r[0]), "=r"(r[1]), "=r"(r[2]), "=r"(r[3]) : "r"(a));
}

__device__ __forceinline__ void mma_f16(float* d, const uint32_t* a,
                                        uint32_t b0, uint32_t b1) {
    asm volatile(
        "mma.sync.aligned.m16n8k16.row.col.f32.f16.f16.f32 "
        "{%0,%1,%2,%3}, {%4,%5,%6,%7}, {%8,%9}, {%0,%1,%2,%3};"
        : "+f"(d[0]), "+f"(d[1]), "+f"(d[2]), "+f"(d[3])
        : "r"(a[0]), "r"(a[1]), "r"(a[2]), "r"(a[3]), "r"(b0), "r"(b1));
}

__device__ __forceinline__ void cpasync16(uint32_t dst, const void* src) {
    asm volatile("cp.async.cg.shared.global [%0], [%1], 16;"
        :: "r"(dst), "l"(src));
}
#define CP_COMMIT() asm volatile("cp.async.commit_group;" ::: "memory")
#define CP_WAIT(n)  asm volatile("cp.async.wait_group %0;" :: "n"(n) : "memory")

// fp32 fast nonlinearities (MUFU EX2 + RCP; ~2 ulp)
__device__ __forceinline__ float sigm_fast(float x) {
    return __fdividef(1.f, 1.f + __expf(-x));
}
__device__ __forceinline__ float tanh_fast(float x) {
    return __fdividef(2.f, 1.f + __expf(-2.f * x)) - 1.f;
}

// ---------------------------------------------------------------------------
// convert_x: fp32 -> fp16 for x only, remapped [N][S][I] -> [S][N][I].
// 262,144 float4 items, grid 1024 x 256.
// ---------------------------------------------------------------------------
__global__ __launch_bounds__(256) void convert_x(const float* __restrict__ mod)
{
    const int i = blockIdx.x * 256 + threadIdx.x;
    int i4 = i & 31, n = (i >> 5) & 1023, s = i >> 15;
    float4 v = *(const float4*)(mod + (size_t)n * (SS * II) + s * II + i4 * 4);
    __half h[4] = {__float2half_rn(v.x), __float2half_rn(v.y),
                   __float2half_rn(v.z), __float2half_rn(v.w)};
    *(uint2*)(g_xh + ((size_t)s * NN + n) * II + i4 * 4) = *(uint2*)h;
}

// ---------------------------------------------------------------------------
// PERSISTENT weight-resident gates kernel + Wout-conversion piggyback.
// Blocks [0,128): one per (s, f0) pair. Prologue loads the 3 gate-weight
//   tiles from fp32, converts to fp16 in smem ONCE; loops over 8 n-tiles
//   with double-buffered cp.async x fill. Warp tile 32(n) x 16(f),
//   512 threads = 16 warps (4x4). Fused LSTM epilogue -> h fp16.
//   smem: 2 x-stages + weights = 121856 B.
// Blocks [128,256): convert Wout fp32 -> g_wouth fp16 (zero smem; co-resident
//   with / filling the 20 gates-free SMs, overlapped with HMMA-bound gates).
// ---------------------------------------------------------------------------
__global__ __launch_bounds__(512, 1) void gates_mma(
    const float* __restrict__ bi, const float* __restrict__ bg,
    const float* __restrict__ bo,
    const float* __restrict__ Wxi, const float* __restrict__ Wxg,
    const float* __restrict__ Wxo, const float* __restrict__ Wout)
{
    const int bx = blockIdx.x;
    const int tid = threadIdx.x;

    if (bx >= 128) {                       // ---- Wout conversion blocks ----
        const int cb = bx - 128;           // 0..127, 8192 float4 each
        const float4* src = (const float4*)Wout;
#pragma unroll
        for (int it = 0; it < 16; it++) {
            size_t j = (size_t)cb * 8192 + it * 512 + tid;
            float4 v = src[j];
            __half h[4] = {__float2half_rn(v.x), __float2half_rn(v.y),
                           __float2half_rn(v.z), __float2half_rn(v.w)};
            *(uint2*)(g_wouth + j * 4) = *(uint2*)h;
        }
        return;
    }

    extern __shared__ __half sm[];
    constexpr int PAD = 136;                      // k-stride (halves), ldsm-clean
    constexpr uint32_t STAGE_E = 128 * PAD;       // x stage, 17408 halves
    constexpr uint32_t OFF_W = 2 * STAGE_E;       // weights: 3 x 64*PAD halves

    const int wid = tid >> 5, lane = tid & 31;
    const int s = bx >> 4, f0 = (bx & 15) * 64;
    const uint32_t sb = smem_u32(sm);

    // ---- x-tile fill (cp.async): 128 rows x 128 halves ----
    auto fill_x = [&](int n0, uint32_t st) {
        const __half* sa = g_xh + ((size_t)s * NN + n0) * II;
#pragma unroll
        for (int it = 0; it < 4; it++) {
            int idx = tid + it * 512;
            int row = idx >> 4, q = idx & 15;
            cpasync16(sb + 2 * (st + row * PAD + q * 8),
                      sa + (size_t)row * II + q * 8);
        }
    };

    fill_x(0, 0);
    CP_COMMIT();

    // ---- weight prologue: fp32 LDG -> cvt -> STS (once per CTA) ----
    {
        const float* WS[3] = {Wxi, Wxg, Wxo};
#pragma unroll
        for (int g = 0; g < 3; g++) {
            const float* wsrc = WS[g] + ((size_t)s * FF + f0) * II;
#pragma unroll
            for (int it = 0; it < 4; it++) {
                int idx = tid + it * 512;          // 2048 float4 per gate
                int row = idx >> 5, q = idx & 31;  // 32 float4 per 128-k row
                float4 v = *(const float4*)(wsrc + (size_t)row * II + q * 4);
                __half h[4] = {__float2half_rn(v.x), __float2half_rn(v.y),
                               __float2half_rn(v.z), __float2half_rn(v.w)};
                *(uint2*)(sm + OFF_W + g * 64 * PAD + row * PAD + q * 4) =
                    *(uint2*)h;
            }
        }
    }

    const int wm = wid & 3, wn = wid >> 2;
    const int lrA = lane & 15, lcA = (lane >> 4) << 3;
    const int lrB = ((lane >> 4) << 3) + (lane & 7), lcB = ((lane >> 3) & 1) << 3;

    // biases: constant per CTA across the n-loop — load once
    const int fc0 = f0 + wn * 16 + (lane & 3) * 2;       // nb = 0
    const int fc1 = fc0 + 8;                             // nb = 1
    const float bia[4] = {bi[(size_t)s * FF + fc0], bi[(size_t)s * FF + fc0 + 1],
                          bi[(size_t)s * FF + fc1], bi[(size_t)s * FF + fc1 + 1]};
    const float bga[4] = {bg[(size_t)s * FF + fc0], bg[(size_t)s * FF + fc0 + 1],
                          bg[(size_t)s * FF + fc1], bg[(size_t)s * FF + fc1 + 1]};
    const float boa[4] = {bo[(size_t)s * FF + fc0], bo[(size_t)s * FF + fc0 + 1],
                          bo[(size_t)s * FF + fc1], bo[(size_t)s * FF + fc1 + 1]};

    int stage = 0;
#pragma unroll 1
    for (int i = 0; i < 8; i++) {
        const int n0 = i * 128;
        if (i + 1 < 8) fill_x(n0 + 128, (uint32_t)(stage ^ 1) * STAGE_E);
        CP_COMMIT();
        CP_WAIT(1);                 // current x stage complete
        __syncthreads();            // also orders the weight STS (first iter)

        const uint32_t st = (uint32_t)stage * STAGE_E;

        float acc[3][2][2][4];
#pragma unroll
        for (int g = 0; g < 3; g++)
#pragma unroll
            for (int mb = 0; mb < 2; mb++)
#pragma unroll
                for (int nb = 0; nb < 2; nb++)
#pragma unroll
                    for (int e = 0; e < 4; e++) acc[g][mb][nb][e] = 0.f;

        const uint32_t aAh = sb + 2 * (st + (wm * 32 + lrA) * PAD + lcA);

#pragma unroll
        for (int kk = 0; kk < 8; kk++) {
            const int k0 = kk * 16;
            uint32_t ah[2][4];
            ldsm4(ah[0], aAh + 2 * k0);
            ldsm4(ah[1], aAh + 2 * (16 * PAD + k0));
#pragma unroll
            for (int g = 0; g < 3; g++) {
                const uint32_t bgb = sb + 2 * (OFF_W + g * 64 * PAD
                                     + (wn * 16 + lrB) * PAD + k0 + lcB);
                uint32_t bh[4];
                ldsm4(bh, bgb);
#pragma unroll
                for (int mb = 0; mb < 2; mb++)
#pragma unroll
                    for (int nb = 0; nb < 2; nb++)
                        mma_f16(acc[g][mb][nb], ah[mb], bh[nb * 2], bh[nb * 2 + 1]);
            }
        }

        // ---- fused LSTM epilogue: h = sigm(o)*tanh(sigm(i)*tanh(g)) ----
#pragma unroll
        for (int nb = 0; nb < 2; nb++) {
            const int fc = (nb == 0) ? fc0 : fc1;
#pragma unroll
            for (int mb = 0; mb < 2; mb++)
#pragma unroll
                for (int hf = 0; hf < 2; hf++) {
                    const int n = n0 + wm * 32 + mb * 16 + (lane >> 2) + hf * 8;
                    const size_t off = ((size_t)s * NN + n) * FF + fc;
                    float h2[2];
#pragma unroll
                    for (int e = 0; e < 2; e++) {
                        float pi = acc[0][mb][nb][hf * 2 + e] + bia[nb * 2 + e];
                        float pg = acc[1][mb][nb][hf * 2 + e] + bga[nb * 2 + e];
                        float po = acc[2][mb][nb][hf * 2 + e] + boa[nb * 2 + e];
                        float cv = sigm_fast(pi) * tanh_fast(pg);
                        h2[e] = sigm_fast(po) * tanh_fast(cv);
                    }
                    *(__half2*)(g_hh + off) = __floats2half2_rn(h2[0], h2[1]);
                }
        }
        __syncthreads();            // all reads of this x stage done
        stage ^= 1;
    }
}

// ---------------------------------------------------------------------------
// Out kernel: CTA tile 128(n) x 128(m). 256 threads = 8 warps (2x4),
// warp tile 64(n) x 32(m). K=1024 in 32 chunks of 32, 4-stage cp.async
// pipeline with ONE sync per iteration. 2 CTAs/SM (smem 81920 B).
// grid (8, 4, 8) -> single wave at 2/SM.
// ---------------------------------------------------------------------------
__global__ __launch_bounds__(256, 2) void out_mma(
    const float* __restrict__ bout, float* __restrict__ out)
{
    extern __shared__ __half sm[];
    constexpr int PB = 40;                         // row stride (80 B, ldsm-clean)
    constexpr uint32_t TEN = 128 * PB;             // elems per tensor per stage
    constexpr uint32_t STG_B = 2u * TEN * 2;       // 20480 B per stage, 4 stages

    const int tid = threadIdx.x, wid = tid >> 5, lane = tid & 31;
    const int s = blockIdx.z, n0 = blockIdx.x * 128, m0 = blockIdx.y * 128;
    const uint32_t sb = smem_u32(sm);

    const __half* gA = g_hh    + ((size_t)s * NN + n0) * FF;
    const __half* gB = g_wouth + ((size_t)s * MM + m0) * FF;

    auto load = [&](int ch, int stg) {
        const int kc = ch * 32;
        const uint32_t base = sb + (uint32_t)stg * STG_B;
#pragma unroll
        for (int it = 0; it < 2; it++) {
            int idx = tid + it * 256;
            int row = idx >> 2, q = idx & 3;
            const uint32_t d = 2 * (row * PB + q * 8);
            const size_t so = (size_t)row * FF + kc + q * 8;
            cpasync16(base + d,           gA + so);
            cpasync16(base + 2 * TEN + d, gB + so);
        }
    };

    const int wm = wid & 1, wn = wid >> 1;
    const int lrA = lane & 15, lcA = (lane >> 4) << 3;
    const int lrB = ((lane >> 4) << 3) + (lane & 7), lcB = ((lane >> 3) & 1) << 3;

    float acc[4][4][4];
#pragma unroll
    for (int mb = 0; mb < 4; mb++)
#pragma unroll
        for (int nb = 0; nb < 4; nb++)
#pragma unroll
            for (int e = 0; e < 4; e++) acc[mb][nb][e] = 0.f;

    load(0, 0); CP_COMMIT();
    load(1, 1); CP_COMMIT();
    load(2, 2); CP_COMMIT();

#pragma unroll 1
    for (int ch = 0; ch < 32; ch++) {
        CP_WAIT(2);
        __syncthreads();
        // sync above also guarantees stage (ch+3)&3 (consumed at ch-1) is free
        if (ch + 3 < 32) load(ch + 3, (ch + 3) & 3);
        CP_COMMIT();

        const int stg = ch & 3;
        const uint32_t base = sb + (uint32_t)stg * STG_B;
        const uint32_t aA = base + 2 * ((wm * 64 + lrA) * PB + lcA);
        const uint32_t aB = base + 2 * (TEN + (wn * 32 + lrB) * PB + lcB);

#pragma unroll
        for (int kk = 0; kk < 2; kk++) {
            const int k0 = kk * 16;
            uint32_t ah[4][4], bh[2][4];
#pragma unroll
            for (int mb = 0; mb < 4; mb++)
                ldsm4(ah[mb], aA + 2 * (mb * 16 * PB + k0));
#pragma unroll
            for (int p = 0; p < 2; p++)
                ldsm4(bh[p], aB + 2 * (p * 16 * PB + k0));
#pragma unroll
            for (int mb = 0; mb < 4; mb++)
#pragma unroll
                for (int nb = 0; nb < 4; nb++)
                    mma_f16(acc[mb][nb], ah[mb],
                            bh[nb >> 1][(nb & 1) * 2], bh[nb >> 1][(nb & 1) * 2 + 1]);
        }
    }

    // ---- epilogue: bias + fp32 store ----
#pragma unroll
    for (int nb = 0; nb < 4; nb++) {
        const int mc = m0 + wn * 32 + nb * 8 + (lane & 3) * 2;
        const float b0 = bout[(size_t)s * MM + mc];
        const float b1 = bout[(size_t)s * MM + mc + 1];
#pragma unroll
        for (int mb = 0; mb < 4; mb++)
#pragma unroll
            for (int hf = 0; hf < 2; hf++) {
                const int n = n0 + wm * 64 + mb * 16 + (lane >> 2) + hf * 8;
                float2 v = make_float2(acc[mb][nb][hf * 2] + b0,
                                       acc[mb][nb][hf * 2 + 1] + b1);
                *(float2*)(out + (size_t)n * (SS * MM) + s * MM + mc) = v;
            }
    }
}

// ---------------------------------------------------------------------------
// Launch. Inputs: modulation, Wxi, Whi, bi, Wxf, Whf, bf, Wxg, Whg, bg,
// Wxo, Who, bo, Wout, bout. h0 = c0 = 0 kills Whi/Wxf/Whf/bf/Whg/Who.
// ---------------------------------------------------------------------------
extern "C" void kernel_launch(void* const* d_in, const int* in_sizes, int n_in,
                              void* d_out, int out_size) {
    const float* mod  = (const float*)d_in[0];
    const float* Wxi  = (const float*)d_in[1];
    const float* bi   = (const float*)d_in[3];
    const float* Wxg  = (const float*)d_in[7];
    const float* bg   = (const float*)d_in[9];
    const float* Wxo  = (const float*)d_in[10];
    const float* bo   = (const float*)d_in[12];
    const float* Wout = (const float*)d_in[13];
    const float* bout = (const float*)d_in[14];
    float* out = (float*)d_out;

    cudaFuncSetAttribute(gates_mma, cudaFuncAttributeMaxDynamicSharedMemorySize, 121856);
    cudaFuncSetAttribute(out_mma,   cudaFuncAttributeMaxDynamicSharedMemorySize, 81920);

    convert_x<<<1024, 256>>>(mod);

    // 128 persistent gates CTAs + 128 Wout-convert blocks in one launch
    gates_mma<<<256, 512, 121856>>>(bi, bg, bo, Wxi, Wxg, Wxo, Wout);

    dim3 gOut(NN / 128, MM / 128, SS);             // (8, 4, 8)
    out_mma<<<gOut, 256, 81920>>>(bout, out);
}

// round 15
// speedup vs baseline: 1.7824x; 1.0065x over previous
#include <cuda_runtime.h>
#include <cuda_fp16.h>
#include <cstdint>
#include <math.h>

#define NN 1024
#define SS 8
#define II 128
#define FF 1024
#define MM 512

// ---------------------------------------------------------------------------
// Scratch (device globals). Pure fp16, single term.
// ---------------------------------------------------------------------------
__device__ __align__(16) __half g_xh[SS * NN * II];
__device__ __align__(16) __half g_wouth[SS * MM * FF];
__device__ __align__(16) __half g_hh[SS * NN * FF];
__device__ int g_xcnt[SS];   // x-slice completion counters (reset by out_mma)

// ---------------------------------------------------------------------------
// Helpers
// ---------------------------------------------------------------------------
__device__ __forceinline__ uint32_t smem_u32(const void* p) {
    uint32_t a;
    asm("{ .reg .u64 t; cvta.to.shared.u64 t, %1; cvt.u32.u64 %0, t; }"
        : "=r"(a) : "l"(p));
    return a;
}

__device__ __forceinline__ void ldsm4(uint32_t* r, uint32_t a) {
    asm volatile("ldmatrix.sync.aligned.m8n8.x4.shared.b16 {%0,%1,%2,%3}, [%4];"
        : "=r"(r[0]), "=r"(r[1]), "=r"(r[2]), "=r"(r[3]) : "r"(a));
}

__device__ __forceinline__ void mma_f16(float* d, const uint32_t* a,
                                        uint32_t b0, uint32_t b1) {
    asm volatile(
        "mma.sync.aligned.m16n8k16.row.col.f32.f16.f16.f32 "
        "{%0,%1,%2,%3}, {%4,%5,%6,%7}, {%8,%9}, {%0,%1,%2,%3};"
        : "+f"(d[0]), "+f"(d[1]), "+f"(d[2]), "+f"(d[3])
        : "r"(a[0]), "r"(a[1]), "r"(a[2]), "r"(a[3]), "r"(b0), "r"(b1));
}

__device__ __forceinline__ void cpasync16(uint32_t dst, const void* src) {
    asm volatile("cp.async.cg.shared.global [%0], [%1], 16;"
        :: "r"(dst), "l"(src));
}
#define CP_COMMIT() asm volatile("cp.async.commit_group;" ::: "memory")
#define CP_WAIT(n)  asm volatile("cp.async.wait_group %0;" :: "n"(n) : "memory")

// fp32 fast nonlinearities (MUFU EX2 + RCP; ~2 ulp)
__device__ __forceinline__ float sigm_fast(float x) {
    return __fdividef(1.f, 1.f + __expf(-x));
}
__device__ __forceinline__ float tanh_fast(float x) {
    return __fdividef(2.f, 1.f + __expf(-2.f * x)) - 1.f;
}

// ---------------------------------------------------------------------------
// PERSISTENT weight-resident gates kernel; x conversion done cooperatively
// inside (no standalone convert kernel).
// Blocks [0,128): one per (s, j): convert x slice (rows j*64..j*64+63 of
//   stream s) fp32->fp16 into g_xh, publish via threadfence+atomic; load the
//   3 gate-weight tiles fp32->fp16 into smem ONCE (overlaps the spin); spin
//   until all 16 slices of stream s are ready; then loop over 8 n-tiles with
//   double-buffered cp.async x fill. Warp tile 32(n) x 16(f), 512 threads.
//   Fused LSTM epilogue -> h fp16. smem 121856 B.
// Blocks [128,256): convert Wout fp32 -> g_wouth fp16 (zero smem, overlapped).
// ---------------------------------------------------------------------------
__global__ __launch_bounds__(512, 1) void gates_mma(
    const float* __restrict__ mod,
    const float* __restrict__ bi, const float* __restrict__ bg,
    const float* __restrict__ bo,
    const float* __restrict__ Wxi, const float* __restrict__ Wxg,
    const float* __restrict__ Wxo, const float* __restrict__ Wout)
{
    const int bx = blockIdx.x;
    const int tid = threadIdx.x;

    if (bx >= 128) {                       // ---- Wout conversion blocks ----
        const int cb = bx - 128;           // 0..127, 8192 float4 each
        const float4* src = (const float4*)Wout;
#pragma unroll
        for (int it = 0; it < 16; it++) {
            size_t j = (size_t)cb * 8192 + it * 512 + tid;
            float4 v = src[j];
            __half h[4] = {__float2half_rn(v.x), __float2half_rn(v.y),
                           __float2half_rn(v.z), __float2half_rn(v.w)};
            *(uint2*)(g_wouth + j * 4) = *(uint2*)h;
        }
        return;
    }

    extern __shared__ __half sm[];
    constexpr int PAD = 136;                      // k-stride (halves), ldsm-clean
    constexpr uint32_t STAGE_E = 128 * PAD;       // x stage, 17408 halves
    constexpr uint32_t OFF_W = 2 * STAGE_E;       // weights: 3 x 64*PAD halves

    const int wid = tid >> 5, lane = tid & 31;
    const int s = bx >> 4, jsl = bx & 15, f0 = jsl * 64;
    const uint32_t sb = smem_u32(sm);

    // ---- convert own x slice: rows [jsl*64, jsl*64+64) of stream s ----
    {
#pragma unroll
        for (int it = 0; it < 4; it++) {
            int idx = tid + it * 512;              // 2048 float4
            int row = jsl * 64 + (idx >> 5), q = idx & 31;
            float4 v = *(const float4*)(mod + (size_t)row * (SS * II)
                                            + s * II + q * 4);
            __half h[4] = {__float2half_rn(v.x), __float2half_rn(v.y),
                           __float2half_rn(v.z), __float2half_rn(v.w)};
            *(uint2*)(g_xh + ((size_t)s * NN + row) * II + q * 4) = *(uint2*)h;
        }
        __threadfence();
        __syncthreads();
        if (tid == 0) atomicAdd(&g_xcnt[s], 1);
    }

    // ---- weight prologue: fp32 LDG -> cvt -> STS (overlaps the spin) ----
    {
        const float* WS[3] = {Wxi, Wxg, Wxo};
#pragma unroll
        for (int g = 0; g < 3; g++) {
            const float* wsrc = WS[g] + ((size_t)s * FF + f0) * II;
#pragma unroll
            for (int it = 0; it < 4; it++) {
                int idx = tid + it * 512;          // 2048 float4 per gate
                int row = idx >> 5, q = idx & 31;
                float4 v = *(const float4*)(wsrc + (size_t)row * II + q * 4);
                __half h[4] = {__float2half_rn(v.x), __float2half_rn(v.y),
                               __float2half_rn(v.z), __float2half_rn(v.w)};
                *(uint2*)(sm + OFF_W + g * 64 * PAD + row * PAD + q * 4) =
                    *(uint2*)h;
            }
        }
    }

    // ---- spin until all 16 slices of stream s are published ----
    if (tid == 0) {
        while (atomicAdd(&g_xcnt[s], 0) < 16) {}
        __threadfence();
    }
    __syncthreads();

    // ---- x-tile fill (cp.async.cg -> L2-coherent): 128 rows x 128 halves ----
    auto fill_x = [&](int n0, uint32_t st) {
        const __half* sa = g_xh + ((size_t)s * NN + n0) * II;
#pragma unroll
        for (int it = 0; it < 4; it++) {
            int idx = tid + it * 512;
            int row = idx >> 4, q = idx & 15;
            cpasync16(sb + 2 * (st + row * PAD + q * 8),
                      sa + (size_t)row * II + q * 8);
        }
    };

    fill_x(0, 0);
    CP_COMMIT();

    const int wm = wid & 3, wn = wid >> 2;
    const int lrA = lane & 15, lcA = (lane >> 4) << 3;
    const int lrB = ((lane >> 4) << 3) + (lane & 7), lcB = ((lane >> 3) & 1) << 3;

    // biases: constant per CTA across the n-loop — load once
    const int fc0 = f0 + wn * 16 + (lane & 3) * 2;
    const int fc1 = fc0 + 8;
    const float bia[4] = {bi[(size_t)s * FF + fc0], bi[(size_t)s * FF + fc0 + 1],
                          bi[(size_t)s * FF + fc1], bi[(size_t)s * FF + fc1 + 1]};
    const float bga[4] = {bg[(size_t)s * FF + fc0], bg[(size_t)s * FF + fc0 + 1],
                          bg[(size_t)s * FF + fc1], bg[(size_t)s * FF + fc1 + 1]};
    const float boa[4] = {bo[(size_t)s * FF + fc0], bo[(size_t)s * FF + fc0 + 1],
                          bo[(size_t)s * FF + fc1], bo[(size_t)s * FF + fc1 + 1]};

    int stage = 0;
#pragma unroll 1
    for (int i = 0; i < 8; i++) {
        const int n0 = i * 128;
        if (i + 1 < 8) fill_x(n0 + 128, (uint32_t)(stage ^ 1) * STAGE_E);
        CP_COMMIT();
        CP_WAIT(1);                 // current x stage complete
        __syncthreads();            // also orders the weight STS (first iter)

        const uint32_t st = (uint32_t)stage * STAGE_E;

        float acc[3][2][2][4];
#pragma unroll
        for (int g = 0; g < 3; g++)
#pragma unroll
            for (int mb = 0; mb < 2; mb++)
#pragma unroll
                for (int nb = 0; nb < 2; nb++)
#pragma unroll
                    for (int e = 0; e < 4; e++) acc[g][mb][nb][e] = 0.f;

        const uint32_t aAh = sb + 2 * (st + (wm * 32 + lrA) * PAD + lcA);

#pragma unroll
        for (int kk = 0; kk < 8; kk++) {
            const int k0 = kk * 16;
            uint32_t ah[2][4];
            ldsm4(ah[0], aAh + 2 * k0);
            ldsm4(ah[1], aAh + 2 * (16 * PAD + k0));
#pragma unroll
            for (int g = 0; g < 3; g++) {
                const uint32_t bgb = sb + 2 * (OFF_W + g * 64 * PAD
                                     + (wn * 16 + lrB) * PAD + k0 + lcB);
                uint32_t bh[4];
                ldsm4(bh, bgb);
#pragma unroll
                for (int mb = 0; mb < 2; mb++)
#pragma unroll
                    for (int nb = 0; nb < 2; nb++)
                        mma_f16(acc[g][mb][nb], ah[mb], bh[nb * 2], bh[nb * 2 + 1]);
            }
        }

        // ---- fused LSTM epilogue: h = sigm(o)*tanh(sigm(i)*tanh(g)) ----
#pragma unroll
        for (int nb = 0; nb < 2; nb++) {
            const int fc = (nb == 0) ? fc0 : fc1;
#pragma unroll
            for (int mb = 0; mb < 2; mb++)
#pragma unroll
                for (int hf = 0; hf < 2; hf++) {
                    const int n = n0 + wm * 32 + mb * 16 + (lane >> 2) + hf * 8;
                    const size_t off = ((size_t)s * NN + n) * FF + fc;
                    float h2[2];
#pragma unroll
                    for (int e = 0; e < 2; e++) {
                        float pi = acc[0][mb][nb][hf * 2 + e] + bia[nb * 2 + e];
                        float pg = acc[1][mb][nb][hf * 2 + e] + bga[nb * 2 + e];
                        float po = acc[2][mb][nb][hf * 2 + e] + boa[nb * 2 + e];
                        float cv = sigm_fast(pi) * tanh_fast(pg);
                        h2[e] = sigm_fast(po) * tanh_fast(cv);
                    }
                    *(__half2*)(g_hh + off) = __floats2half2_rn(h2[0], h2[1]);
                }
        }
        __syncthreads();            // all reads of this x stage done
        stage ^= 1;
    }
}

// ---------------------------------------------------------------------------
// Out kernel: CTA tile 128(n) x 128(m). 256 threads = 8 warps (2x4),
// warp tile 64(n) x 32(m). K=1024 in 16 chunks of 64, 3-stage cp.async
// pipeline with ONE sync per iteration. 2 CTAs/SM (smem 110592 B).
// Also resets g_xcnt for the next graph replay (block (0,0,0)).
// ---------------------------------------------------------------------------
__global__ __launch_bounds__(256, 2) void out_mma(
    const float* __restrict__ bout, float* __restrict__ out)
{
    extern __shared__ __half sm[];
    constexpr int PB = 72;                         // 64-chunk row stride, clean
    constexpr uint32_t TEN = 128 * PB;             // 9216 halves per tensor
    constexpr uint32_t STG_B = 2u * TEN * 2;       // 36864 B per stage, 3 stages

    const int tid = threadIdx.x, wid = tid >> 5, lane = tid & 31;
    const int s = blockIdx.z, n0 = blockIdx.x * 128, m0 = blockIdx.y * 128;
    const uint32_t sb = smem_u32(sm);

    // reset x-slice counters for next replay (any thread order is fine)
    if (blockIdx.x == 0 && blockIdx.y == 0 && blockIdx.z == 0 && tid < SS)
        g_xcnt[tid] = 0;

    const __half* gA = g_hh    + ((size_t)s * NN + n0) * FF;
    const __half* gB = g_wouth + ((size_t)s * MM + m0) * FF;

    auto load = [&](int ch, int stg) {
        const int kc = ch * 64;
        const uint32_t base = sb + (uint32_t)stg * STG_B;
#pragma unroll
        for (int it = 0; it < 4; it++) {
            int idx = tid + it * 256;              // 1024 positions
            int row = idx >> 3, q = idx & 7;       // 128 rows x 8 x 16B
            const uint32_t d = 2 * (row * PB + q * 8);
            const size_t so = (size_t)row * FF + kc + q * 8;
            cpasync16(base + d,           gA + so);
            cpasync16(base + 2 * TEN + d, gB + so);
        }
    };

    const int wm = wid & 1, wn = wid >> 1;
    const int lrA = lane & 15, lcA = (lane >> 4) << 3;
    const int lrB = ((lane >> 4) << 3) + (lane & 7), lcB = ((lane >> 3) & 1) << 3;

    float acc[4][4][4];
#pragma unroll
    for (int mb = 0; mb < 4; mb++)
#pragma unroll
        for (int nb = 0; nb < 4; nb++)
#pragma unroll
            for (int e = 0; e < 4; e++) acc[mb][nb][e] = 0.f;

    load(0, 0); CP_COMMIT();
    load(1, 1); CP_COMMIT();

#pragma unroll 1
    for (int ch = 0; ch < 16; ch++) {
        CP_WAIT(1);
        __syncthreads();
        // stage (ch+2)%3 == stage (ch-1)%3 was fully read at iter ch-1
        if (ch + 2 < 16) load(ch + 2, (ch + 2) % 3);
        CP_COMMIT();

        const int stg = ch % 3;
        const uint32_t base = sb + (uint32_t)stg * STG_B;
        const uint32_t aA = base + 2 * ((wm * 64 + lrA) * PB + lcA);
        const uint32_t aB = base + 2 * (TEN + (wn * 32 + lrB) * PB + lcB);

#pragma unroll
        for (int kk = 0; kk < 4; kk++) {
            const int k0 = kk * 16;
            uint32_t ah[4][4], bh[2][4];
#pragma unroll
            for (int mb = 0; mb < 4; mb++)
                ldsm4(ah[mb], aA + 2 * (mb * 16 * PB + k0));
#pragma unroll
            for (int p = 0; p < 2; p++)
                ldsm4(bh[p], aB + 2 * (p * 16 * PB + k0));
#pragma unroll
            for (int mb = 0; mb < 4; mb++)
#pragma unroll
                for (int nb = 0; nb < 4; nb++)
                    mma_f16(acc[mb][nb], ah[mb],
                            bh[nb >> 1][(nb & 1) * 2], bh[nb >> 1][(nb & 1) * 2 + 1]);
        }
    }

    // ---- epilogue: bias + fp32 store ----
#pragma unroll
    for (int nb = 0; nb < 4; nb++) {
        const int mc = m0 + wn * 32 + nb * 8 + (lane & 3) * 2;
        const float b0 = bout[(size_t)s * MM + mc];
        const float b1 = bout[(size_t)s * MM + mc + 1];
#pragma unroll
        for (int mb = 0; mb < 4; mb++)
#pragma unroll
            for (int hf = 0; hf < 2; hf++) {
                const int n = n0 + wm * 64 + mb * 16 + (lane >> 2) + hf * 8;
                float2 v = make_float2(acc[mb][nb][hf * 2] + b0,
                                       acc[mb][nb][hf * 2 + 1] + b1);
                *(float2*)(out + (size_t)n * (SS * MM) + s * MM + mc) = v;
            }
    }
}

// ---------------------------------------------------------------------------
// Launch. Inputs: modulation, Wxi, Whi, bi, Wxf, Whf, bf, Wxg, Whg, bg,
// Wxo, Who, bo, Wout, bout. h0 = c0 = 0 kills Whi/Wxf/Whf/bf/Whg/Who.
// ---------------------------------------------------------------------------
extern "C" void kernel_launch(void* const* d_in, const int* in_sizes, int n_in,
                              void* d_out, int out_size) {
    const float* mod  = (const float*)d_in[0];
    const float* Wxi  = (const float*)d_in[1];
    const float* bi   = (const float*)d_in[3];
    const float* Wxg  = (const float*)d_in[7];
    const float* bg   = (const float*)d_in[9];
    const float* Wxo  = (const float*)d_in[10];
    const float* bo   = (const float*)d_in[12];
    const float* Wout = (const float*)d_in[13];
    const float* bout = (const float*)d_in[14];
    float* out = (float*)d_out;

    cudaFuncSetAttribute(gates_mma, cudaFuncAttributeMaxDynamicSharedMemorySize, 121856);
    cudaFuncSetAttribute(out_mma,   cudaFuncAttributeMaxDynamicSharedMemorySize, 110592);

    // 128 persistent gates CTAs (with in-kernel x convert) + 128 Wout blocks
    gates_mma<<<256, 512, 121856>>>(mod, bi, bg, bo, Wxi, Wxg, Wxo, Wout);

    dim3 gOut(NN / 128, MM / 128, SS);             // (8, 4, 8)
    out_mma<<<gOut, 256, 110592>>>(bout, out);
}